// round 5
// baseline (speedup 1.0000x reference)
#include <cuda_runtime.h>
#include <math.h>

#define B_   2048
#define DIN_ 768
#define D_   512
#define H_   8
#define HD_  64
#define L_   3
#define P_   40
#define Q_   128
#define EPSF 1e-5f

// ---------------- scratch (device globals; no allocation allowed) ----------------
__device__ float g_feat0[B_ * D_];
__device__ float g_feat [B_ * D_];
__device__ float g_buf1 [B_ * D_];
__device__ float g_buf2 [B_ * D_];
__device__ float g_qkv  [B_ * 3 * D_];
__device__ float g_part [2 * B_ * D_];     // key-split unnormalized O partials
__device__ float2 g_ml  [2 * B_ * H_];     // key-split (m, l) per row/head
__device__ float g_z    [B_ * Q_];

// ---------------- helpers ----------------
__device__ __forceinline__ float to_tf32(float x) {
    float r; asm("cvt.rna.tf32.f32 %0, %1;" : "=f"(r) : "f"(x)); return r;
}
__device__ __forceinline__ void mma_tf32(float* c, unsigned a0, unsigned a1,
                                         unsigned a2, unsigned a3,
                                         unsigned b0, unsigned b1) {
    asm volatile(
        "mma.sync.aligned.m16n8k8.row.col.f32.tf32.tf32.f32 "
        "{%0,%1,%2,%3}, {%4,%5,%6,%7}, {%8,%9}, {%0,%1,%2,%3};"
        : "+f"(c[0]), "+f"(c[1]), "+f"(c[2]), "+f"(c[3])
        : "r"(a0), "r"(a1), "r"(a2), "r"(a3), "r"(b0), "r"(b1));
}
__device__ __forceinline__ void mma_bf16(float* c, unsigned a0, unsigned a1,
                                         unsigned a2, unsigned a3,
                                         unsigned b0, unsigned b1) {
    asm volatile(
        "mma.sync.aligned.m16n8k16.row.col.f32.bf16.bf16.f32 "
        "{%0,%1,%2,%3}, {%4,%5,%6,%7}, {%8,%9}, {%0,%1,%2,%3};"
        : "+f"(c[0]), "+f"(c[1]), "+f"(c[2]), "+f"(c[3])
        : "r"(a0), "r"(a1), "r"(a2), "r"(a3), "r"(b0), "r"(b1));
}
__device__ __forceinline__ unsigned pack_bf16(float lo, float hi) {
    unsigned r; asm("cvt.rn.bf16x2.f32 %0, %1, %2;" : "=r"(r) : "f"(hi), "f"(lo));
    return r;
}
__device__ __forceinline__ constexpr int permk(int k) { return (k & 3) * 4 + (k >> 2); }

#define AS_RS 20   // row stride (floats) for perm-K tiles in the dense GEMMs

// ================= tf32 MMA GEMM, TN: C = alpha*(A @ W^T) [+bias][+relu][+res] ========
template<int BN, int EPI>
__global__ __launch_bounds__(256)
void gemm_mma_tn(const float* __restrict__ A, const float* __restrict__ W,
                 const float* __restrict__ bias, const float* __restrict__ res,
                 float* __restrict__ C, int K, int lda, int ldw, int ldc,
                 long sA, long sW, long sC, float alpha)
{
    constexpr int NT = BN / 16;
    A += (long)blockIdx.z * sA;
    W += (long)blockIdx.z * sW;
    C += (long)blockIdx.z * sC;
    __shared__ float As[128][AS_RS];
    __shared__ float Ws[BN][AS_RS];

    const int tid = threadIdx.x;
    const int w = tid >> 5, lb = tid & 31, g = lb >> 2, t = lb & 3;
    const int wm = (w >> 1) * 32, wn = (w & 1) * (BN / 2);
    const int m0 = blockIdx.y * 128, n0 = blockIdx.x * BN;
    const int srow = tid >> 1, skb = (tid & 1) * 8;
    const bool wact = (BN == 128) || (tid < 128);

    float4 ra0 = *(const float4*)&A[(size_t)(m0 + srow) * lda + skb];
    float4 ra1 = *(const float4*)&A[(size_t)(m0 + srow) * lda + skb + 4];
    float4 rw0 = {0,0,0,0}, rw1 = {0,0,0,0};
    if (wact) {
        rw0 = *(const float4*)&W[(size_t)(n0 + srow) * ldw + skb];
        rw1 = *(const float4*)&W[(size_t)(n0 + srow) * ldw + skb + 4];
    }

    float acc[2][NT][4];
    #pragma unroll
    for (int mt = 0; mt < 2; mt++)
        #pragma unroll
        for (int nt = 0; nt < NT; nt++)
            #pragma unroll
            for (int i = 0; i < 4; i++) acc[mt][nt][i] = 0.f;

    for (int k0 = 0; k0 < K; k0 += 16) {
        {
            float va[8] = {ra0.x, ra0.y, ra0.z, ra0.w, ra1.x, ra1.y, ra1.z, ra1.w};
            #pragma unroll
            for (int i = 0; i < 8; i++) As[srow][permk(skb + i)] = to_tf32(va[i]);
            if (wact) {
                float vw[8] = {rw0.x, rw0.y, rw0.z, rw0.w, rw1.x, rw1.y, rw1.z, rw1.w};
                #pragma unroll
                for (int i = 0; i < 8; i++) Ws[srow][permk(skb + i)] = to_tf32(vw[i]);
            }
        }
        __syncthreads();
        if (k0 + 16 < K) {
            ra0 = *(const float4*)&A[(size_t)(m0 + srow) * lda + k0 + 16 + skb];
            ra1 = *(const float4*)&A[(size_t)(m0 + srow) * lda + k0 + 16 + skb + 4];
            if (wact) {
                rw0 = *(const float4*)&W[(size_t)(n0 + srow) * ldw + k0 + 16 + skb];
                rw1 = *(const float4*)&W[(size_t)(n0 + srow) * ldw + k0 + 16 + skb + 4];
            }
        }
        uint4 Af[4];
        Af[0] = *(const uint4*)&As[wm + g     ][4 * t];
        Af[1] = *(const uint4*)&As[wm + g + 8 ][4 * t];
        Af[2] = *(const uint4*)&As[wm + g + 16][4 * t];
        Af[3] = *(const uint4*)&As[wm + g + 24][4 * t];
        #pragma unroll
        for (int nt = 0; nt < NT; nt++) {
            uint4 Bf = *(const uint4*)&Ws[wn + 8 * nt + g][4 * t];
            mma_tf32(acc[0][nt], Af[0].x, Af[1].x, Af[0].y, Af[1].y, Bf.x, Bf.y);
            mma_tf32(acc[1][nt], Af[2].x, Af[3].x, Af[2].y, Af[3].y, Bf.x, Bf.y);
            mma_tf32(acc[0][nt], Af[0].z, Af[1].z, Af[0].w, Af[1].w, Bf.z, Bf.w);
            mma_tf32(acc[1][nt], Af[2].z, Af[3].z, Af[2].w, Af[3].w, Bf.z, Bf.w);
        }
        __syncthreads();
    }

    #pragma unroll
    for (int mt = 0; mt < 2; mt++) {
        const int r0 = m0 + wm + 16 * mt + g;
        #pragma unroll
        for (int nt = 0; nt < NT; nt++) {
            const int n = n0 + wn + 8 * nt + 2 * t;
            #pragma unroll
            for (int half = 0; half < 2; half++) {
                const int r = r0 + 8 * half;
                const size_t ro = (size_t)r * ldc;
                float2 v = { acc[mt][nt][2 * half], acc[mt][nt][2 * half + 1] };
                v.x *= alpha; v.y *= alpha;
                if (bias) { v.x += bias[n]; v.y += bias[n + 1]; }
                if (EPI == 1) { v.x = fmaxf(v.x, 0.f); v.y = fmaxf(v.y, 0.f); }
                if (EPI == 2) { v.x += res[ro + n]; v.y += res[ro + n + 1]; }
                *(float2*)&C[ro + n] = v;
            }
        }
    }
}

// ================= fused flash attention, bf16 MMA, key-split =================
// grid (32 q-tiles, 8 heads, 2 key-splits), 128 threads (4 warps x 16 q-rows).
// Within a 16-dim group, pairs are stored in order (0,1)(8,9)(2,3)(10,11)(4,5)(12,13)(6,7)(14,15)
// so that lane t's B/A fragment {2t,2t+1,2t+8,2t+9} is one 8-byte LDS.
#define KROWB 160   // bytes per K-tile row (64 bf16 + pad); row-start banks differ by 8
#define VROWB 288   // bytes per V^T row (128 bf16 + pad)

__device__ __forceinline__ int pos16(int k16) {   // k16 even
    return ((k16 & 7) >> 1) * 4 + ((k16 >> 3) & 1) * 2;
}

__global__ __launch_bounds__(128, 3)
void attn_fused(const float* __restrict__ qkv, float* __restrict__ outp,
                float2* __restrict__ ml)
{
    __shared__ unsigned char smem[128 * KROWB + 64 * VROWB];
    unsigned char* Ks = smem;
    unsigned char* Vs = smem + 128 * KROWB;

    const int tid = threadIdx.x;
    const int w = tid >> 5, ln = tid & 31, g = ln >> 2, t = ln & 3;
    const int h = blockIdx.y;
    const int q0 = blockIdx.x * 64;
    const int z = blockIdx.z;

    // ---- stage Q (pre-scaled by 1/8) as bf16 into Ks rows 0..63 ----
    {
        const int r = tid >> 1, half = (tid & 1) * 32;
        const float* qp = qkv + (size_t)(q0 + r) * 1536 + h * 64 + half;
        unsigned char* dst = Ks + r * KROWB;
        #pragma unroll
        for (int j = 0; j < 8; j++) {
            float4 v = *(const float4*)(qp + 4 * j);
            int k = half + 4 * j;
            int kg = k >> 4, p = pos16(k & 15);
            unsigned* pp = (unsigned*)(dst + kg * 32 + p * 2);
            pp[0] = pack_bf16(v.x * 0.125f, v.y * 0.125f);
            pp[2] = pack_bf16(v.z * 0.125f, v.w * 0.125f);
        }
    }
    __syncthreads();
    unsigned qa[4][4];
    #pragma unroll
    for (int kg = 0; kg < 4; kg++) {
        uint2 f0 = *(const uint2*)(Ks + (16 * w + g)     * KROWB + kg * 32 + t * 8);
        uint2 f1 = *(const uint2*)(Ks + (16 * w + g + 8) * KROWB + kg * 32 + t * 8);
        qa[kg][0] = f0.x; qa[kg][2] = f0.y;
        qa[kg][1] = f1.x; qa[kg][3] = f1.y;
    }

    float m0r = -1e30f, m1r = -1e30f, l0r = 0.f, l1r = 0.f;
    float o[8][4];
    #pragma unroll
    for (int nt = 0; nt < 8; nt++)
        #pragma unroll
        for (int i = 0; i < 4; i++) o[nt][i] = 0.f;

    for (int kt = z * 8; kt < z * 8 + 8; kt++) {
        __syncthreads();
        // ---- stage K tile (128 keys x 64 dims, bf16) ----
        {
            const int r = tid;   // one thread per key row
            const float* kp = qkv + (size_t)(kt * 128 + r) * 1536 + 512 + h * 64;
            unsigned char* dst = Ks + r * KROWB;
            #pragma unroll
            for (int j = 0; j < 16; j++) {
                float4 v = *(const float4*)(kp + 4 * j);
                int k = 4 * j;
                int kg = k >> 4, p = pos16(k & 15);
                unsigned* pp = (unsigned*)(dst + kg * 32 + p * 2);
                pp[0] = pack_bf16(v.x, v.y);
                pp[2] = pack_bf16(v.z, v.w);
            }
        }
        // ---- stage V^T tile (64 dims x 128 keys, bf16) ----
        {
            const int kpair = tid & 63, dg = tid >> 6;
            const float* v0p = qkv + (size_t)(kt * 128 + 2 * kpair) * 1536 + 1024 + h * 64 + dg * 32;
            const float* v1p = v0p + 1536;
            const int kgv = kpair >> 3;
            const int p = pos16((2 * kpair) & 15);
            unsigned char* base = Vs + kgv * 32 + p * 2;
            #pragma unroll
            for (int j = 0; j < 8; j++) {
                float4 va = *(const float4*)(v0p + 4 * j);
                float4 vb = *(const float4*)(v1p + 4 * j);
                int d = dg * 32 + 4 * j;
                *(unsigned*)(base + (d + 0) * VROWB) = pack_bf16(va.x, vb.x);
                *(unsigned*)(base + (d + 1) * VROWB) = pack_bf16(va.y, vb.y);
                *(unsigned*)(base + (d + 2) * VROWB) = pack_bf16(va.z, vb.z);
                *(unsigned*)(base + (d + 3) * VROWB) = pack_bf16(va.w, vb.w);
            }
        }
        __syncthreads();

        // ---- S = Q @ K^T (16 rows x 128 keys per warp) ----
        float s[16][4];
        #pragma unroll
        for (int nt = 0; nt < 16; nt++)
            #pragma unroll
            for (int i = 0; i < 4; i++) s[nt][i] = 0.f;
        #pragma unroll
        for (int kg = 0; kg < 4; kg++) {
            #pragma unroll
            for (int nt = 0; nt < 16; nt++) {
                uint2 b = *(const uint2*)(Ks + (8 * nt + g) * KROWB + kg * 32 + t * 8);
                mma_bf16(s[nt], qa[kg][0], qa[kg][1], qa[kg][2], qa[kg][3], b.x, b.y);
            }
        }

        // ---- online softmax ----
        float mx0 = -1e30f, mx1 = -1e30f;
        #pragma unroll
        for (int nt = 0; nt < 16; nt++) {
            mx0 = fmaxf(mx0, fmaxf(s[nt][0], s[nt][1]));
            mx1 = fmaxf(mx1, fmaxf(s[nt][2], s[nt][3]));
        }
        mx0 = fmaxf(mx0, __shfl_xor_sync(0xffffffffu, mx0, 1));
        mx0 = fmaxf(mx0, __shfl_xor_sync(0xffffffffu, mx0, 2));
        mx1 = fmaxf(mx1, __shfl_xor_sync(0xffffffffu, mx1, 1));
        mx1 = fmaxf(mx1, __shfl_xor_sync(0xffffffffu, mx1, 2));
        const float mn0 = fmaxf(m0r, mx0), mn1 = fmaxf(m1r, mx1);
        const float al0 = __expf(m0r - mn0), al1 = __expf(m1r - mn1);
        m0r = mn0; m1r = mn1;
        float sum0 = 0.f, sum1 = 0.f;
        #pragma unroll
        for (int nt = 0; nt < 16; nt++) {
            s[nt][0] = __expf(s[nt][0] - mn0);
            s[nt][1] = __expf(s[nt][1] - mn0);
            s[nt][2] = __expf(s[nt][2] - mn1);
            s[nt][3] = __expf(s[nt][3] - mn1);
            sum0 += s[nt][0] + s[nt][1];
            sum1 += s[nt][2] + s[nt][3];
        }
        sum0 += __shfl_xor_sync(0xffffffffu, sum0, 1);
        sum0 += __shfl_xor_sync(0xffffffffu, sum0, 2);
        sum1 += __shfl_xor_sync(0xffffffffu, sum1, 1);
        sum1 += __shfl_xor_sync(0xffffffffu, sum1, 2);
        l0r = l0r * al0 + sum0;
        l1r = l1r * al1 + sum1;
        #pragma unroll
        for (int nt = 0; nt < 8; nt++) {
            o[nt][0] *= al0; o[nt][1] *= al0;
            o[nt][2] *= al1; o[nt][3] *= al1;
        }

        // ---- pack P to bf16 A-fragments (C-layout == A-layout, no shuffles) ----
        unsigned pa[8][4];
        #pragma unroll
        for (int kg = 0; kg < 8; kg++) {
            pa[kg][0] = pack_bf16(s[2 * kg][0],     s[2 * kg][1]);
            pa[kg][1] = pack_bf16(s[2 * kg][2],     s[2 * kg][3]);
            pa[kg][2] = pack_bf16(s[2 * kg + 1][0], s[2 * kg + 1][1]);
            pa[kg][3] = pack_bf16(s[2 * kg + 1][2], s[2 * kg + 1][3]);
        }

        // ---- O += P @ V ----
        #pragma unroll
        for (int kg = 0; kg < 8; kg++) {
            #pragma unroll
            for (int nt = 0; nt < 8; nt++) {
                uint2 b = *(const uint2*)(Vs + (8 * nt + g) * VROWB + kg * 32 + t * 8);
                mma_bf16(o[nt], pa[kg][0], pa[kg][1], pa[kg][2], pa[kg][3], b.x, b.y);
            }
        }
    }

    // ---- write unnormalized partials + (m, l) ----
    float* op = outp + (size_t)z * (B_ * D_);
    #pragma unroll
    for (int nt = 0; nt < 8; nt++) {
        const int n = h * 64 + 8 * nt + 2 * t;
        const size_t r0 = (size_t)(q0 + 16 * w + g) * D_;
        const size_t r1 = (size_t)(q0 + 16 * w + g + 8) * D_;
        *(float2*)&op[r0 + n] = make_float2(o[nt][0], o[nt][1]);
        *(float2*)&op[r1 + n] = make_float2(o[nt][2], o[nt][3]);
    }
    if (t == 0) {
        ml[((size_t)z * B_ + q0 + 16 * w + g)     * H_ + h] = make_float2(m0r, l0r);
        ml[((size_t)z * B_ + q0 + 16 * w + g + 8) * H_ + h] = make_float2(m1r, l1r);
    }
}

// ---------------- combine the two key-split partials ----------------
__global__ __launch_bounds__(256)
void attn_combine(const float* __restrict__ outp, const float2* __restrict__ ml,
                  float* __restrict__ ctx)
{
    const int token = blockIdx.x;
    const int d = threadIdx.x * 2;
    const int h = d >> 6;
    float2 p1 = ml[(size_t)token * H_ + h];
    float2 p2 = ml[((size_t)B_ + token) * H_ + h];
    float m = fmaxf(p1.x, p2.x);
    float w1 = __expf(p1.x - m), w2 = __expf(p2.x - m);
    float inv = 1.0f / (p1.y * w1 + p2.y * w2);
    float2 o1 = *(const float2*)&outp[(size_t)token * D_ + d];
    float2 o2 = *(const float2*)&outp[(size_t)(B_ + token) * D_ + d];
    float2 r = { (o1.x * w1 + o2.x * w2) * inv, (o1.y * w1 + o2.y * w2) * inv };
    *(float2*)&ctx[(size_t)token * D_ + d] = r;
}

// ---------------- per-row normalize (LN if AFFINE, InstanceNorm otherwise) ----------------
template<int N, bool AFFINE, bool ADD>
__global__ __launch_bounds__(128)
void rownorm(const float* __restrict__ src, const float* __restrict__ addv,
             const float* __restrict__ w, const float* __restrict__ bb,
             float* __restrict__ dst, float* __restrict__ dst2)
{
    constexpr int NPT = N / 128;
    const size_t base = (size_t)blockIdx.x * N;
    const int t = threadIdx.x;
    float v[NPT];
    float s = 0.f;
    #pragma unroll
    for (int i = 0; i < NPT; i++) { v[i] = src[base + t + i * 128]; s += v[i]; }
    __shared__ float sm[4];
    #pragma unroll
    for (int o = 16; o > 0; o >>= 1) s += __shfl_xor_sync(0xffffffffu, s, o);
    if ((t & 31) == 0) sm[t >> 5] = s;
    __syncthreads();
    s = sm[0] + sm[1] + sm[2] + sm[3];
    const float mean = s * (1.0f / N);
    float q = 0.f;
    #pragma unroll
    for (int i = 0; i < NPT; i++) { float d = v[i] - mean; q += d * d; }
    __syncthreads();
    #pragma unroll
    for (int o = 16; o > 0; o >>= 1) q += __shfl_xor_sync(0xffffffffu, q, o);
    if ((t & 31) == 0) sm[t >> 5] = q;
    __syncthreads();
    q = sm[0] + sm[1] + sm[2] + sm[3];
    const float r = rsqrtf(q * (1.0f / N) + EPSF);
    #pragma unroll
    for (int i = 0; i < NPT; i++) {
        int c = t + i * 128;
        float y = (v[i] - mean) * r;
        if (AFFINE) y = y * w[c] + bb[c];
        if (ADD)    y += addv[base + c];
        dst[base + c] = y;
        if (dst2) dst2[base + c] = y;
    }
}

// ---------------- cdist to prototypes, min over P, logits ----------------
__global__ __launch_bounds__(128)
void cdist_logits(const float* __restrict__ z, const float* __restrict__ hi,
                  const float* __restrict__ neg, float* __restrict__ out)
{
    __shared__ float zr[Q_];
    __shared__ float dist[128];
    const int b = blockIdx.x, t = threadIdx.x;
    zr[t] = z[(size_t)b * Q_ + t];
    dist[t] = 3.4e38f;
    __syncthreads();
    if (t < P_) {
        const float* p = hi + (size_t)t * Q_;
        float s = 0.f;
        #pragma unroll 8
        for (int d = 0; d < Q_; d++) { float df = zr[d] - p[d]; s = fmaf(df, df, s); }
        dist[t] = sqrtf(s);
    } else if (t >= 64 && t < 64 + P_) {
        const float* p = neg + (size_t)(t - 64) * Q_;
        float s = 0.f;
        #pragma unroll 8
        for (int d = 0; d < Q_; d++) { float df = zr[d] - p[d]; s = fmaf(df, df, s); }
        dist[t] = sqrtf(s);
    }
    __syncthreads();
    if (t == 0) {
        float m = 3.4e38f;
        for (int i = 0; i < P_; i++) m = fminf(m, dist[i]);
        out[b * 2 + 1] = -m;      // -positive_dist
    }
    if (t == 32) {
        float m = 3.4e38f;
        for (int i = 0; i < P_; i++) m = fminf(m, dist[64 + i]);
        out[b * 2 + 0] = -m;      // -negative_dist
    }
}

// ---------------- host driver ----------------
extern "C" void kernel_launch(void* const* d_in, const int* in_sizes, int n_in,
                              void* d_out, int out_size)
{
    const float* x        = (const float*)d_in[0];
    const float* reduce_w = (const float*)d_in[1];
    const float* reduce_b = (const float*)d_in[2];
    const float* in_w     = (const float*)d_in[3];
    const float* in_b     = (const float*)d_in[4];
    const float* out_w    = (const float*)d_in[5];
    const float* out_b    = (const float*)d_in[6];
    const float* ff1_w    = (const float*)d_in[7];
    const float* ff1_b    = (const float*)d_in[8];
    const float* ff2_w    = (const float*)d_in[9];
    const float* ff2_b    = (const float*)d_in[10];
    const float* ln1_w    = (const float*)d_in[11];
    const float* ln1_b    = (const float*)d_in[12];
    const float* ln2_w    = (const float*)d_in[13];
    const float* ln2_b    = (const float*)d_in[14];
    const float* mlp_w1   = (const float*)d_in[15];
    const float* mlp_b1   = (const float*)d_in[16];
    const float* mlp_w2   = (const float*)d_in[17];
    const float* mlp_b2   = (const float*)d_in[18];
    const float* mlp_w3   = (const float*)d_in[19];
    const float* mlp_b3   = (const float*)d_in[20];
    const float* highlights = (const float*)d_in[21];
    const float* negatives  = (const float*)d_in[22];
    float* out = (float*)d_out;

    float *feat0, *feat, *buf1, *buf2, *qkv, *part, *z;
    float2* ml;
    cudaGetSymbolAddress((void**)&feat0, g_feat0);
    cudaGetSymbolAddress((void**)&feat,  g_feat);
    cudaGetSymbolAddress((void**)&buf1,  g_buf1);
    cudaGetSymbolAddress((void**)&buf2,  g_buf2);
    cudaGetSymbolAddress((void**)&qkv,   g_qkv);
    cudaGetSymbolAddress((void**)&part,  g_part);
    cudaGetSymbolAddress((void**)&ml,    g_ml);
    cudaGetSymbolAddress((void**)&z,     g_z);

    const dim3 blk(256);

    // feat0 = inorm(x @ reduce_w^T + b);  feat = feat0
    gemm_mma_tn<64, 0><<<dim3(D_ / 64, B_ / 128, 1), blk>>>(
        x, reduce_w, reduce_b, nullptr, buf1, DIN_, DIN_, DIN_, D_, 0, 0, 0, 1.f);
    rownorm<D_, false, false><<<B_, 128>>>(buf1, nullptr, nullptr, nullptr, feat0, feat);

    for (int l = 0; l < L_; l++) {
        // qkv = feat @ in_w^T + in_b
        gemm_mma_tn<128, 0><<<dim3(3 * D_ / 128, B_ / 128, 1), blk>>>(
            feat, in_w + (size_t)l * 3 * D_ * D_, in_b + l * 3 * D_, nullptr, qkv,
            D_, D_, D_, 3 * D_, 0, 0, 0, 1.f);
        // fused attention (bf16, key-split) -> partials; combine -> buf2 (ctx)
        attn_fused<<<dim3(B_ / 64, H_, 2), 128>>>(qkv, part, ml);
        attn_combine<<<B_, 256>>>(part, ml, buf2);
        // attn_out + residual -> buf1 ; LN1 -> feat
        gemm_mma_tn<64, 2><<<dim3(D_ / 64, B_ / 128, 1), blk>>>(
            buf2, out_w + (size_t)l * D_ * D_, out_b + l * D_, feat, buf1,
            D_, D_, D_, D_, 0, 0, 0, 1.f);
        rownorm<D_, true, false><<<B_, 128>>>(buf1, nullptr, ln1_w + l * D_, ln1_b + l * D_, feat, nullptr);
        // FFN
        gemm_mma_tn<64, 1><<<dim3(D_ / 64, B_ / 128, 1), blk>>>(
            feat, ff1_w + (size_t)l * D_ * D_, ff1_b + l * D_, nullptr, buf2,
            D_, D_, D_, D_, 0, 0, 0, 1.f);
        gemm_mma_tn<64, 2><<<dim3(D_ / 64, B_ / 128, 1), blk>>>(
            buf2, ff2_w + (size_t)l * D_ * D_, ff2_b + l * D_, feat, buf1,
            D_, D_, D_, D_, 0, 0, 0, 1.f);
        rownorm<D_, true, false><<<B_, 128>>>(buf1, nullptr, ln2_w + l * D_, ln2_b + l * D_, feat, nullptr);
    }

    // feat = feat0 + inorm(feat)  -> buf1
    rownorm<D_, false, true><<<B_, 128>>>(feat, feat0, nullptr, nullptr, buf1, nullptr);

    // MLP: 512 -> 512 -> 512 -> 128
    gemm_mma_tn<64, 1><<<dim3(D_ / 64, B_ / 128, 1), blk>>>(
        buf1, mlp_w1, mlp_b1, nullptr, buf2, D_, D_, D_, D_, 0, 0, 0, 1.f);
    gemm_mma_tn<64, 1><<<dim3(D_ / 64, B_ / 128, 1), blk>>>(
        buf2, mlp_w2, mlp_b2, nullptr, buf1, D_, D_, D_, D_, 0, 0, 0, 1.f);
    gemm_mma_tn<64, 0><<<dim3(Q_ / 64, B_ / 128, 1), blk>>>(
        buf1, mlp_w3, mlp_b3, nullptr, buf2, D_, D_, D_, Q_, 0, 0, 0, 1.f);
    rownorm<Q_, false, false><<<B_, 128>>>(buf2, nullptr, nullptr, nullptr, z, nullptr);

    cdist_logits<<<B_, 128>>>(z, highlights, negatives, out);
}

// round 6
// speedup vs baseline: 1.2142x; 1.2142x over previous
#include <cuda_runtime.h>
#include <cuda_bf16.h>
#include <math.h>

#define B_   2048
#define DIN_ 768
#define D_   512
#define H_   8
#define HD_  64
#define L_   3
#define P_   40
#define Q_   128
#define EPSF 1e-5f

// ---------------- scratch (device globals; no allocation allowed) ----------------
__device__ float g_feat0[B_ * D_];
__device__ float g_feat [B_ * D_];
__device__ float g_buf1 [B_ * D_];
__device__ float g_buf2 [B_ * D_];
__device__ float g_qkv  [B_ * 3 * D_];
__device__ float g_part [2 * B_ * D_];     // key-split unnormalized O partials
__device__ float2 g_ml  [2 * B_ * H_];     // key-split (m, l) per row/head
__device__ float g_z    [B_ * Q_];
__device__ __nv_bfloat16 g_wbf[5800000];   // bf16 weight pool

// weight pool offsets (elements)
#define OFF_RED  0
#define OFF_IN   (OFF_RED + D_ * DIN_)                 // 393216
#define OFF_OUT  (OFF_IN + L_ * 3 * D_ * D_)           // +2359296
#define OFF_FF1  (OFF_OUT + L_ * D_ * D_)
#define OFF_FF2  (OFF_FF1 + L_ * D_ * D_)
#define OFF_M1   (OFF_FF2 + L_ * D_ * D_)
#define OFF_M2   (OFF_M1 + D_ * D_)
#define OFF_M3   (OFF_M2 + D_ * D_)

// ---------------- helpers ----------------
__device__ __forceinline__ void mma_bf16(float* c, unsigned a0, unsigned a1,
                                         unsigned a2, unsigned a3,
                                         unsigned b0, unsigned b1) {
    asm volatile(
        "mma.sync.aligned.m16n8k16.row.col.f32.bf16.bf16.f32 "
        "{%0,%1,%2,%3}, {%4,%5,%6,%7}, {%8,%9}, {%0,%1,%2,%3};"
        : "+f"(c[0]), "+f"(c[1]), "+f"(c[2]), "+f"(c[3])
        : "r"(a0), "r"(a1), "r"(a2), "r"(a3), "r"(b0), "r"(b1));
}
__device__ __forceinline__ unsigned pack_bf16(float lo, float hi) {
    unsigned r; asm("cvt.rn.bf16x2.f32 %0, %1, %2;" : "=r"(r) : "f"(hi), "f"(lo));
    return r;
}
// within a 16-k group (even k): byte position/2 of the bf16 pair (k,k+1)
__device__ __forceinline__ int pos16(int k16) {
    return ((k16 & 7) >> 1) * 4 + ((k16 >> 3) & 1) * 2;
}

// ---------------- fp32 -> bf16 weight conversion ----------------
__global__ __launch_bounds__(256)
void cvt_bf16(const float* __restrict__ in, __nv_bfloat16* __restrict__ out, int n4)
{
    int i = blockIdx.x * 256 + threadIdx.x;
    if (i < n4) {
        float4 v = ((const float4*)in)[i];
        uint2 r;
        r.x = pack_bf16(v.x, v.y);
        r.y = pack_bf16(v.z, v.w);
        ((uint2*)out)[i] = r;
    }
}

// ================= bf16 MMA GEMM, TN: C = A @ W^T [+bias][+relu][+res] =================
// A:[M,K] fp32 (lda=K), W:[N,K] bf16, C:[M,N] (ldc). BM=128, BK=32.
// EPI: 0 = bias, 1 = bias+relu, 2 = bias+residual
template<int BN, int EPI>
__global__ __launch_bounds__(256)
void gemm_bf16_tn(const float* __restrict__ A, const __nv_bfloat16* __restrict__ W,
                  const float* __restrict__ bias, const float* __restrict__ res,
                  float* __restrict__ C, int K, int ldc)
{
    constexpr int NT = BN / 16;            // n8 tiles per warp
    constexpr int WROWS = 128 + BN;
    __shared__ unsigned char sm[2 * WROWS * 80];

    const int tid = threadIdx.x;
    const int w = tid >> 5, ln = tid & 31, g = ln >> 2, t = ln & 3;
    const int wm = (w >> 1) * 32, wn = (w & 1) * (BN / 2);
    const int m0 = blockIdx.y * 128, n0 = blockIdx.x * BN;

    const int arow = tid >> 1, akb = (tid & 1) * 16;
    const int wrow = (BN == 128) ? (tid >> 1) : (tid >> 2);
    const int wkb  = (BN == 128) ? ((tid & 1) * 16) : ((tid & 3) * 8);

    const float* ap = A + (size_t)(m0 + arow) * K + akb;
    const __nv_bfloat16* wp = W + (size_t)(n0 + wrow) * K + wkb;

    float acc[2][NT][4];
    #pragma unroll
    for (int mt = 0; mt < 2; mt++)
        #pragma unroll
        for (int nt = 0; nt < NT; nt++)
            #pragma unroll
            for (int i = 0; i < 4; i++) acc[mt][nt][i] = 0.f;

    float4 ra[4];
    uint4 rw0, rw1;

    const int NKT = K / 32;

    // ---- prologue: load + store tile 0 ----
    #pragma unroll
    for (int j = 0; j < 4; j++) ra[j] = *(const float4*)(ap + 4 * j);
    rw0 = *(const uint4*)(wp);
    if (BN == 128) rw1 = *(const uint4*)(wp + 8);

    int cur = 0;
    {
        unsigned char* As = sm;
        unsigned char* Ws = sm + 128 * 80;
        unsigned char* da = As + arow * 80 + (akb >> 4) * 32;
        #pragma unroll
        for (int j = 0; j < 4; j++) {
            int p = pos16(4 * j) * 2;
            *(unsigned*)(da + p)     = pack_bf16(ra[j].x, ra[j].y);
            *(unsigned*)(da + p + 8) = pack_bf16(ra[j].z, ra[j].w);
        }
        unsigned char* dw = Ws + wrow * 80 + (wkb >> 4) * 32;
        if (BN == 128) {
            *(unsigned*)(dw + 0)  = rw0.x; *(unsigned*)(dw + 8)  = rw0.y;
            *(unsigned*)(dw + 16) = rw0.z; *(unsigned*)(dw + 24) = rw0.w;
            *(unsigned*)(dw + 4)  = rw1.x; *(unsigned*)(dw + 12) = rw1.y;
            *(unsigned*)(dw + 20) = rw1.z; *(unsigned*)(dw + 28) = rw1.w;
        } else {
            int b0 = (wkb & 8) ? 4 : 0;
            *(unsigned*)(dw + b0 + 0)  = rw0.x; *(unsigned*)(dw + b0 + 8)  = rw0.y;
            *(unsigned*)(dw + b0 + 16) = rw0.z; *(unsigned*)(dw + b0 + 24) = rw0.w;
        }
    }
    __syncthreads();

    for (int kt = 0; kt < NKT; kt++) {
        if (kt + 1 < NKT) {
            const int k0 = (kt + 1) * 32;
            #pragma unroll
            for (int j = 0; j < 4; j++) ra[j] = *(const float4*)(ap + k0 + 4 * j);
            rw0 = *(const uint4*)(wp + k0);
            if (BN == 128) rw1 = *(const uint4*)(wp + k0 + 8);
        }
        // ---- compute from buffer cur ----
        {
            unsigned char* As = sm + cur * (WROWS * 80);
            unsigned char* Ws = As + 128 * 80;
            #pragma unroll
            for (int kg = 0; kg < 2; kg++) {
                unsigned a[2][4];
                #pragma unroll
                for (int mt = 0; mt < 2; mt++) {
                    uint2 f0 = *(const uint2*)(As + (wm + 16 * mt + g)     * 80 + kg * 32 + t * 8);
                    uint2 f1 = *(const uint2*)(As + (wm + 16 * mt + g + 8) * 80 + kg * 32 + t * 8);
                    a[mt][0] = f0.x; a[mt][1] = f1.x; a[mt][2] = f0.y; a[mt][3] = f1.y;
                }
                #pragma unroll
                for (int nt = 0; nt < NT; nt++) {
                    uint2 b = *(const uint2*)(Ws + (wn + 8 * nt + g) * 80 + kg * 32 + t * 8);
                    mma_bf16(acc[0][nt], a[0][0], a[0][1], a[0][2], a[0][3], b.x, b.y);
                    mma_bf16(acc[1][nt], a[1][0], a[1][1], a[1][2], a[1][3], b.x, b.y);
                }
            }
        }
        if (kt + 1 < NKT) {
            unsigned char* As = sm + (cur ^ 1) * (WROWS * 80);
            unsigned char* Ws = As + 128 * 80;
            unsigned char* da = As + arow * 80 + (akb >> 4) * 32;
            #pragma unroll
            for (int j = 0; j < 4; j++) {
                int p = pos16(4 * j) * 2;
                *(unsigned*)(da + p)     = pack_bf16(ra[j].x, ra[j].y);
                *(unsigned*)(da + p + 8) = pack_bf16(ra[j].z, ra[j].w);
            }
            unsigned char* dw = Ws + wrow * 80 + (wkb >> 4) * 32;
            if (BN == 128) {
                *(unsigned*)(dw + 0)  = rw0.x; *(unsigned*)(dw + 8)  = rw0.y;
                *(unsigned*)(dw + 16) = rw0.z; *(unsigned*)(dw + 24) = rw0.w;
                *(unsigned*)(dw + 4)  = rw1.x; *(unsigned*)(dw + 12) = rw1.y;
                *(unsigned*)(dw + 20) = rw1.z; *(unsigned*)(dw + 28) = rw1.w;
            } else {
                int b0 = (wkb & 8) ? 4 : 0;
                *(unsigned*)(dw + b0 + 0)  = rw0.x; *(unsigned*)(dw + b0 + 8)  = rw0.y;
                *(unsigned*)(dw + b0 + 16) = rw0.z; *(unsigned*)(dw + b0 + 24) = rw0.w;
            }
            __syncthreads();
            cur ^= 1;
        }
    }

    #pragma unroll
    for (int mt = 0; mt < 2; mt++) {
        const int r0 = m0 + wm + 16 * mt + g;
        #pragma unroll
        for (int nt = 0; nt < NT; nt++) {
            const int n = n0 + wn + 8 * nt + 2 * t;
            #pragma unroll
            for (int half = 0; half < 2; half++) {
                const size_t ro = (size_t)(r0 + 8 * half) * ldc;
                float2 v = { acc[mt][nt][2 * half], acc[mt][nt][2 * half + 1] };
                if (bias) { v.x += bias[n]; v.y += bias[n + 1]; }
                if (EPI == 1) { v.x = fmaxf(v.x, 0.f); v.y = fmaxf(v.y, 0.f); }
                if (EPI == 2) { v.x += res[ro + n]; v.y += res[ro + n + 1]; }
                *(float2*)&C[ro + n] = v;
            }
        }
    }
}

// ================= fused flash attention, bf16 MMA, key-split =================
#define KROWB 160   // bytes per K-tile row (64 bf16 + pad)
#define VROWB 288   // bytes per V^T row (128 bf16 + pad)

__global__ __launch_bounds__(128, 3)
void attn_fused(const float* __restrict__ qkv, float* __restrict__ outp,
                float2* __restrict__ ml)
{
    __shared__ unsigned char smem[128 * KROWB + 64 * VROWB];
    unsigned char* Ks = smem;
    unsigned char* Vs = smem + 128 * KROWB;

    const int tid = threadIdx.x;
    const int w = tid >> 5, ln = tid & 31, g = ln >> 2, t = ln & 3;
    const int h = blockIdx.y;
    const int q0 = blockIdx.x * 64;
    const int z = blockIdx.z;

    // ---- stage Q (pre-scaled by 1/8) as bf16 into Ks rows 0..63 ----
    {
        const int r = tid >> 1, half = (tid & 1) * 32;
        const float* qp = qkv + (size_t)(q0 + r) * 1536 + h * 64 + half;
        unsigned char* dst = Ks + r * KROWB;
        #pragma unroll
        for (int j = 0; j < 8; j++) {
            float4 v = *(const float4*)(qp + 4 * j);
            int k = half + 4 * j;
            int kg = k >> 4, p = pos16(k & 15);
            unsigned* pp = (unsigned*)(dst + kg * 32 + p * 2);
            pp[0] = pack_bf16(v.x * 0.125f, v.y * 0.125f);
            pp[2] = pack_bf16(v.z * 0.125f, v.w * 0.125f);
        }
    }
    __syncthreads();
    unsigned qa[4][4];
    #pragma unroll
    for (int kg = 0; kg < 4; kg++) {
        uint2 f0 = *(const uint2*)(Ks + (16 * w + g)     * KROWB + kg * 32 + t * 8);
        uint2 f1 = *(const uint2*)(Ks + (16 * w + g + 8) * KROWB + kg * 32 + t * 8);
        qa[kg][0] = f0.x; qa[kg][2] = f0.y;
        qa[kg][1] = f1.x; qa[kg][3] = f1.y;
    }

    float m0r = -1e30f, m1r = -1e30f, l0r = 0.f, l1r = 0.f;
    float o[8][4];
    #pragma unroll
    for (int nt = 0; nt < 8; nt++)
        #pragma unroll
        for (int i = 0; i < 4; i++) o[nt][i] = 0.f;

    for (int kt = z * 8; kt < z * 8 + 8; kt++) {
        __syncthreads();
        // ---- stage K tile ----
        {
            const int r = tid;
            const float* kp = qkv + (size_t)(kt * 128 + r) * 1536 + 512 + h * 64;
            unsigned char* dst = Ks + r * KROWB;
            #pragma unroll
            for (int j = 0; j < 16; j++) {
                float4 v = *(const float4*)(kp + 4 * j);
                int k = 4 * j;
                int kg = k >> 4, p = pos16(k & 15);
                unsigned* pp = (unsigned*)(dst + kg * 32 + p * 2);
                pp[0] = pack_bf16(v.x, v.y);
                pp[2] = pack_bf16(v.z, v.w);
            }
        }
        // ---- stage V^T tile ----
        {
            const int kpair = tid & 63, dg = tid >> 6;
            const float* v0p = qkv + (size_t)(kt * 128 + 2 * kpair) * 1536 + 1024 + h * 64 + dg * 32;
            const float* v1p = v0p + 1536;
            const int kgv = kpair >> 3;
            const int p = pos16((2 * kpair) & 15);
            unsigned char* base = Vs + kgv * 32 + p * 2;
            #pragma unroll
            for (int j = 0; j < 8; j++) {
                float4 va = *(const float4*)(v0p + 4 * j);
                float4 vb = *(const float4*)(v1p + 4 * j);
                int d = dg * 32 + 4 * j;
                *(unsigned*)(base + (d + 0) * VROWB) = pack_bf16(va.x, vb.x);
                *(unsigned*)(base + (d + 1) * VROWB) = pack_bf16(va.y, vb.y);
                *(unsigned*)(base + (d + 2) * VROWB) = pack_bf16(va.z, vb.z);
                *(unsigned*)(base + (d + 3) * VROWB) = pack_bf16(va.w, vb.w);
            }
        }
        __syncthreads();

        // ---- S = Q @ K^T ----
        float s[16][4];
        #pragma unroll
        for (int nt = 0; nt < 16; nt++)
            #pragma unroll
            for (int i = 0; i < 4; i++) s[nt][i] = 0.f;
        #pragma unroll
        for (int kg = 0; kg < 4; kg++) {
            #pragma unroll
            for (int nt = 0; nt < 16; nt++) {
                uint2 b = *(const uint2*)(Ks + (8 * nt + g) * KROWB + kg * 32 + t * 8);
                mma_bf16(s[nt], qa[kg][0], qa[kg][1], qa[kg][2], qa[kg][3], b.x, b.y);
            }
        }

        // ---- online softmax ----
        float mx0 = -1e30f, mx1 = -1e30f;
        #pragma unroll
        for (int nt = 0; nt < 16; nt++) {
            mx0 = fmaxf(mx0, fmaxf(s[nt][0], s[nt][1]));
            mx1 = fmaxf(mx1, fmaxf(s[nt][2], s[nt][3]));
        }
        mx0 = fmaxf(mx0, __shfl_xor_sync(0xffffffffu, mx0, 1));
        mx0 = fmaxf(mx0, __shfl_xor_sync(0xffffffffu, mx0, 2));
        mx1 = fmaxf(mx1, __shfl_xor_sync(0xffffffffu, mx1, 1));
        mx1 = fmaxf(mx1, __shfl_xor_sync(0xffffffffu, mx1, 2));
        const float mn0 = fmaxf(m0r, mx0), mn1 = fmaxf(m1r, mx1);
        const float al0 = __expf(m0r - mn0), al1 = __expf(m1r - mn1);
        m0r = mn0; m1r = mn1;
        float sum0 = 0.f, sum1 = 0.f;
        #pragma unroll
        for (int nt = 0; nt < 16; nt++) {
            s[nt][0] = __expf(s[nt][0] - mn0);
            s[nt][1] = __expf(s[nt][1] - mn0);
            s[nt][2] = __expf(s[nt][2] - mn1);
            s[nt][3] = __expf(s[nt][3] - mn1);
            sum0 += s[nt][0] + s[nt][1];
            sum1 += s[nt][2] + s[nt][3];
        }
        sum0 += __shfl_xor_sync(0xffffffffu, sum0, 1);
        sum0 += __shfl_xor_sync(0xffffffffu, sum0, 2);
        sum1 += __shfl_xor_sync(0xffffffffu, sum1, 1);
        sum1 += __shfl_xor_sync(0xffffffffu, sum1, 2);
        l0r = l0r * al0 + sum0;
        l1r = l1r * al1 + sum1;
        #pragma unroll
        for (int nt = 0; nt < 8; nt++) {
            o[nt][0] *= al0; o[nt][1] *= al0;
            o[nt][2] *= al1; o[nt][3] *= al1;
        }

        // ---- pack P (C-layout == A-layout) ----
        unsigned pa[8][4];
        #pragma unroll
        for (int kg = 0; kg < 8; kg++) {
            pa[kg][0] = pack_bf16(s[2 * kg][0],     s[2 * kg][1]);
            pa[kg][1] = pack_bf16(s[2 * kg][2],     s[2 * kg][3]);
            pa[kg][2] = pack_bf16(s[2 * kg + 1][0], s[2 * kg + 1][1]);
            pa[kg][3] = pack_bf16(s[2 * kg + 1][2], s[2 * kg + 1][3]);
        }

        // ---- O += P @ V ----
        #pragma unroll
        for (int kg = 0; kg < 8; kg++) {
            #pragma unroll
            for (int nt = 0; nt < 8; nt++) {
                uint2 b = *(const uint2*)(Vs + (8 * nt + g) * VROWB + kg * 32 + t * 8);
                mma_bf16(o[nt], pa[kg][0], pa[kg][1], pa[kg][2], pa[kg][3], b.x, b.y);
            }
        }
    }

    // ---- write unnormalized partials + (m, l) ----
    float* op = outp + (size_t)z * (B_ * D_);
    #pragma unroll
    for (int nt = 0; nt < 8; nt++) {
        const int n = h * 64 + 8 * nt + 2 * t;
        const size_t r0 = (size_t)(q0 + 16 * w + g) * D_;
        const size_t r1 = (size_t)(q0 + 16 * w + g + 8) * D_;
        *(float2*)&op[r0 + n] = make_float2(o[nt][0], o[nt][1]);
        *(float2*)&op[r1 + n] = make_float2(o[nt][2], o[nt][3]);
    }
    if (t == 0) {
        ml[((size_t)z * B_ + q0 + 16 * w + g)     * H_ + h] = make_float2(m0r, l0r);
        ml[((size_t)z * B_ + q0 + 16 * w + g + 8) * H_ + h] = make_float2(m1r, l1r);
    }
}

// ---------------- combine the two key-split partials ----------------
__global__ __launch_bounds__(256)
void attn_combine(const float* __restrict__ outp, const float2* __restrict__ ml,
                  float* __restrict__ ctx)
{
    const int token = blockIdx.x;
    const int d = threadIdx.x * 2;
    const int h = d >> 6;
    float2 p1 = ml[(size_t)token * H_ + h];
    float2 p2 = ml[((size_t)B_ + token) * H_ + h];
    float m = fmaxf(p1.x, p2.x);
    float w1 = __expf(p1.x - m), w2 = __expf(p2.x - m);
    float inv = 1.0f / (p1.y * w1 + p2.y * w2);
    float2 o1 = *(const float2*)&outp[(size_t)token * D_ + d];
    float2 o2 = *(const float2*)&outp[(size_t)(B_ + token) * D_ + d];
    float2 r = { (o1.x * w1 + o2.x * w2) * inv, (o1.y * w1 + o2.y * w2) * inv };
    *(float2*)&ctx[(size_t)token * D_ + d] = r;
}

// ---------------- per-row normalize (LN if AFFINE, InstanceNorm otherwise) ----------------
template<int N, bool AFFINE, bool ADD>
__global__ __launch_bounds__(128)
void rownorm(const float* __restrict__ src, const float* __restrict__ addv,
             const float* __restrict__ w, const float* __restrict__ bb,
             float* __restrict__ dst, float* __restrict__ dst2)
{
    constexpr int NPT = N / 128;
    const size_t base = (size_t)blockIdx.x * N;
    const int t = threadIdx.x;
    float v[NPT];
    float s = 0.f;
    #pragma unroll
    for (int i = 0; i < NPT; i++) { v[i] = src[base + t + i * 128]; s += v[i]; }
    __shared__ float sm[4];
    #pragma unroll
    for (int o = 16; o > 0; o >>= 1) s += __shfl_xor_sync(0xffffffffu, s, o);
    if ((t & 31) == 0) sm[t >> 5] = s;
    __syncthreads();
    s = sm[0] + sm[1] + sm[2] + sm[3];
    const float mean = s * (1.0f / N);
    float q = 0.f;
    #pragma unroll
    for (int i = 0; i < NPT; i++) { float d = v[i] - mean; q += d * d; }
    __syncthreads();
    #pragma unroll
    for (int o = 16; o > 0; o >>= 1) q += __shfl_xor_sync(0xffffffffu, q, o);
    if ((t & 31) == 0) sm[t >> 5] = q;
    __syncthreads();
    q = sm[0] + sm[1] + sm[2] + sm[3];
    const float r = rsqrtf(q * (1.0f / N) + EPSF);
    #pragma unroll
    for (int i = 0; i < NPT; i++) {
        int c = t + i * 128;
        float y = (v[i] - mean) * r;
        if (AFFINE) y = y * w[c] + bb[c];
        if (ADD)    y += addv[base + c];
        dst[base + c] = y;
        if (dst2) dst2[base + c] = y;
    }
}

// ---------------- cdist to prototypes, min over P, logits ----------------
__global__ __launch_bounds__(128)
void cdist_logits(const float* __restrict__ z, const float* __restrict__ hi,
                  const float* __restrict__ neg, float* __restrict__ out)
{
    __shared__ float zr[Q_];
    __shared__ float dist[128];
    const int b = blockIdx.x, t = threadIdx.x;
    zr[t] = z[(size_t)b * Q_ + t];
    dist[t] = 3.4e38f;
    __syncthreads();
    if (t < P_) {
        const float* p = hi + (size_t)t * Q_;
        float s = 0.f;
        #pragma unroll 8
        for (int d = 0; d < Q_; d++) { float df = zr[d] - p[d]; s = fmaf(df, df, s); }
        dist[t] = sqrtf(s);
    } else if (t >= 64 && t < 64 + P_) {
        const float* p = neg + (size_t)(t - 64) * Q_;
        float s = 0.f;
        #pragma unroll 8
        for (int d = 0; d < Q_; d++) { float df = zr[d] - p[d]; s = fmaf(df, df, s); }
        dist[t] = sqrtf(s);
    }
    __syncthreads();
    if (t == 0) {
        float m = 3.4e38f;
        for (int i = 0; i < P_; i++) m = fminf(m, dist[i]);
        out[b * 2 + 1] = -m;
    }
    if (t == 32) {
        float m = 3.4e38f;
        for (int i = 0; i < P_; i++) m = fminf(m, dist[64 + i]);
        out[b * 2 + 0] = -m;
    }
}

// ---------------- host driver ----------------
extern "C" void kernel_launch(void* const* d_in, const int* in_sizes, int n_in,
                              void* d_out, int out_size)
{
    const float* x        = (const float*)d_in[0];
    const float* reduce_w = (const float*)d_in[1];
    const float* reduce_b = (const float*)d_in[2];
    const float* in_w     = (const float*)d_in[3];
    const float* in_b     = (const float*)d_in[4];
    const float* out_w    = (const float*)d_in[5];
    const float* out_b    = (const float*)d_in[6];
    const float* ff1_w    = (const float*)d_in[7];
    const float* ff1_b    = (const float*)d_in[8];
    const float* ff2_w    = (const float*)d_in[9];
    const float* ff2_b    = (const float*)d_in[10];
    const float* ln1_w    = (const float*)d_in[11];
    const float* ln1_b    = (const float*)d_in[12];
    const float* ln2_w    = (const float*)d_in[13];
    const float* ln2_b    = (const float*)d_in[14];
    const float* mlp_w1   = (const float*)d_in[15];
    const float* mlp_b1   = (const float*)d_in[16];
    const float* mlp_w2   = (const float*)d_in[17];
    const float* mlp_b2   = (const float*)d_in[18];
    const float* mlp_w3   = (const float*)d_in[19];
    const float* mlp_b3   = (const float*)d_in[20];
    const float* highlights = (const float*)d_in[21];
    const float* negatives  = (const float*)d_in[22];
    float* out = (float*)d_out;

    float *feat0, *feat, *buf1, *buf2, *qkv, *part, *z;
    float2* ml;
    __nv_bfloat16* wbf;
    cudaGetSymbolAddress((void**)&feat0, g_feat0);
    cudaGetSymbolAddress((void**)&feat,  g_feat);
    cudaGetSymbolAddress((void**)&buf1,  g_buf1);
    cudaGetSymbolAddress((void**)&buf2,  g_buf2);
    cudaGetSymbolAddress((void**)&qkv,   g_qkv);
    cudaGetSymbolAddress((void**)&part,  g_part);
    cudaGetSymbolAddress((void**)&ml,    g_ml);
    cudaGetSymbolAddress((void**)&z,     g_z);
    cudaGetSymbolAddress((void**)&wbf,   g_wbf);

    // ---- convert all weights to bf16 ----
    #define CVT(src, off, n) cvt_bf16<<<((n) / 4 + 255) / 256, 256>>>(src, wbf + (off), (n) / 4)
    CVT(reduce_w, OFF_RED, D_ * DIN_);
    CVT(in_w,     OFF_IN,  L_ * 3 * D_ * D_);
    CVT(out_w,    OFF_OUT, L_ * D_ * D_);
    CVT(ff1_w,    OFF_FF1, L_ * D_ * D_);
    CVT(ff2_w,    OFF_FF2, L_ * D_ * D_);
    CVT(mlp_w1,   OFF_M1,  D_ * D_);
    CVT(mlp_w2,   OFF_M2,  D_ * D_);
    CVT(mlp_w3,   OFF_M3,  Q_ * D_);
    #undef CVT

    const dim3 blk(256);

    // feat0 = inorm(x @ reduce_w^T + b);  feat = feat0
    gemm_bf16_tn<64, 0><<<dim3(D_ / 64, B_ / 128), blk>>>(
        x, wbf + OFF_RED, reduce_b, nullptr, buf1, DIN_, D_);
    rownorm<D_, false, false><<<B_, 128>>>(buf1, nullptr, nullptr, nullptr, feat0, feat);

    for (int l = 0; l < L_; l++) {
        gemm_bf16_tn<128, 0><<<dim3(3 * D_ / 128, B_ / 128), blk>>>(
            feat, wbf + OFF_IN + (size_t)l * 3 * D_ * D_, in_b + l * 3 * D_, nullptr,
            qkv, D_, 3 * D_);
        attn_fused<<<dim3(B_ / 64, H_, 2), 128>>>(qkv, part, ml);
        attn_combine<<<B_, 256>>>(part, ml, buf2);
        gemm_bf16_tn<64, 2><<<dim3(D_ / 64, B_ / 128), blk>>>(
            buf2, wbf + OFF_OUT + (size_t)l * D_ * D_, out_b + l * D_, feat, buf1, D_, D_);
        rownorm<D_, true, false><<<B_, 128>>>(buf1, nullptr, ln1_w + l * D_, ln1_b + l * D_, feat, nullptr);
        gemm_bf16_tn<64, 1><<<dim3(D_ / 64, B_ / 128), blk>>>(
            feat, wbf + OFF_FF1 + (size_t)l * D_ * D_, ff1_b + l * D_, nullptr, buf2, D_, D_);
        gemm_bf16_tn<64, 2><<<dim3(D_ / 64, B_ / 128), blk>>>(
            buf2, wbf + OFF_FF2 + (size_t)l * D_ * D_, ff2_b + l * D_, feat, buf1, D_, D_);
        rownorm<D_, true, false><<<B_, 128>>>(buf1, nullptr, ln2_w + l * D_, ln2_b + l * D_, feat, nullptr);
    }

    // feat = feat0 + inorm(feat)  -> buf1
    rownorm<D_, false, true><<<B_, 128>>>(feat, feat0, nullptr, nullptr, buf1, nullptr);

    // MLP: 512 -> 512 -> 512 -> 128
    gemm_bf16_tn<64, 1><<<dim3(D_ / 64, B_ / 128), blk>>>(
        buf1, wbf + OFF_M1, mlp_b1, nullptr, buf2, D_, D_);
    gemm_bf16_tn<64, 1><<<dim3(D_ / 64, B_ / 128), blk>>>(
        buf2, wbf + OFF_M2, mlp_b2, nullptr, buf1, D_, D_);
    gemm_bf16_tn<64, 0><<<dim3(Q_ / 64, B_ / 128), blk>>>(
        buf1, wbf + OFF_M3, mlp_b3, nullptr, buf2, D_, Q_);
    rownorm<Q_, false, false><<<B_, 128>>>(buf2, nullptr, nullptr, nullptr, z, nullptr);

    cdist_logits<<<B_, 128>>>(z, highlights, negatives, out);
}

// round 7
// speedup vs baseline: 1.6449x; 1.3547x over previous
#include <cuda_runtime.h>
#include <cuda_bf16.h>
#include <math.h>

#define B_   2048
#define DIN_ 768
#define D_   512
#define H_   8
#define HD_  64
#define L_   3
#define P_   40
#define Q_   128
#define EPSF 1e-5f

// ---------------- scratch (device globals; no allocation allowed) ----------------
__device__ float g_feat0[B_ * D_];
__device__ float g_feat [B_ * D_];
__device__ float g_buf1 [B_ * D_];
__device__ float g_buf2 [B_ * D_];
__device__ __nv_bfloat16 g_qkvb[B_ * 3 * D_];   // bf16 qkv (q pre-scaled by 1/8)
__device__ float g_part [2 * B_ * D_];           // key-split unnormalized O partials
__device__ float2 g_ml  [2 * B_ * H_];           // key-split (m, l) per row/head
__device__ float g_z    [B_ * Q_];
__device__ __nv_bfloat16 g_wbf[5800000];         // bf16 weight pool

// weight pool offsets (elements)
#define OFF_RED  0
#define OFF_IN   (OFF_RED + D_ * DIN_)
#define OFF_OUT  (OFF_IN + L_ * 3 * D_ * D_)
#define OFF_FF1  (OFF_OUT + L_ * D_ * D_)
#define OFF_FF2  (OFF_FF1 + L_ * D_ * D_)
#define OFF_M1   (OFF_FF2 + L_ * D_ * D_)
#define OFF_M2   (OFF_M1 + D_ * D_)
#define OFF_M3   (OFF_M2 + D_ * D_)

// ---------------- helpers ----------------
__device__ __forceinline__ void mma_bf16(float* c, unsigned a0, unsigned a1,
                                         unsigned a2, unsigned a3,
                                         unsigned b0, unsigned b1) {
    asm volatile(
        "mma.sync.aligned.m16n8k16.row.col.f32.bf16.bf16.f32 "
        "{%0,%1,%2,%3}, {%4,%5,%6,%7}, {%8,%9}, {%0,%1,%2,%3};"
        : "+f"(c[0]), "+f"(c[1]), "+f"(c[2]), "+f"(c[3])
        : "r"(a0), "r"(a1), "r"(a2), "r"(a3), "r"(b0), "r"(b1));
}
__device__ __forceinline__ unsigned pack_bf16(float lo, float hi) {
    unsigned r; asm("cvt.rn.bf16x2.f32 %0, %1, %2;" : "=r"(r) : "f"(hi), "f"(lo));
    return r;
}
__device__ __forceinline__ int pos16(int k16) {
    return ((k16 & 7) >> 1) * 4 + ((k16 >> 3) & 1) * 2;
}
__device__ __forceinline__ void ldsm_x4(unsigned& a, unsigned& b, unsigned& c,
                                        unsigned& d, unsigned p) {
    asm volatile("ldmatrix.sync.aligned.m8n8.x4.shared.b16 {%0,%1,%2,%3}, [%4];"
                 : "=r"(a), "=r"(b), "=r"(c), "=r"(d) : "r"(p));
}
__device__ __forceinline__ void ldsm_x4t(unsigned& a, unsigned& b, unsigned& c,
                                         unsigned& d, unsigned p) {
    asm volatile("ldmatrix.sync.aligned.m8n8.x4.trans.shared.b16 {%0,%1,%2,%3}, [%4];"
                 : "=r"(a), "=r"(b), "=r"(c), "=r"(d) : "r"(p));
}
__device__ __forceinline__ void cp16(unsigned dst, const void* src) {
    asm volatile("cp.async.cg.shared.global [%0], [%1], 16;" :: "r"(dst), "l"(src));
}

// ---------------- fp32 -> bf16 weight conversion ----------------
__global__ __launch_bounds__(256)
void cvt_bf16(const float* __restrict__ in, __nv_bfloat16* __restrict__ out, int n4)
{
    int i = blockIdx.x * 256 + threadIdx.x;
    if (i < n4) {
        float4 v = ((const float4*)in)[i];
        uint2 r;
        r.x = pack_bf16(v.x, v.y);
        r.y = pack_bf16(v.z, v.w);
        ((uint2*)out)[i] = r;
    }
}

// ================= bf16 MMA GEMM, TN: C = A @ W^T [+bias][+relu][+res] =================
// A:[M,K] fp32, W:[N,K] bf16. BM=128, BK=32.
// EPI: 0 = bias, 1 = bias+relu, 2 = bias+residual
// OUT: 0 = fp32 out; 1 = bf16 out with cols<512 scaled by 0.125 (qkv)
template<int BN, int EPI, int OUT>
__global__ __launch_bounds__(256)
void gemm_bf16_tn(const float* __restrict__ A, const __nv_bfloat16* __restrict__ W,
                  const float* __restrict__ bias, const float* __restrict__ res,
                  void* __restrict__ Cv, int K, int ldc)
{
    constexpr int NT = BN / 16;
    constexpr int WROWS = 128 + BN;
    __shared__ unsigned char sm[2 * WROWS * 80];

    const int tid = threadIdx.x;
    const int w = tid >> 5, ln = tid & 31, g = ln >> 2, t = ln & 3;
    const int wm = (w >> 1) * 32, wn = (w & 1) * (BN / 2);
    const int m0 = blockIdx.y * 128, n0 = blockIdx.x * BN;

    const int arow = tid >> 1, akb = (tid & 1) * 16;
    const int wrow = (BN == 128) ? (tid >> 1) : (tid >> 2);
    const int wkb  = (BN == 128) ? ((tid & 1) * 16) : ((tid & 3) * 8);

    const float* ap = A + (size_t)(m0 + arow) * K + akb;
    const __nv_bfloat16* wp = W + (size_t)(n0 + wrow) * K + wkb;

    float acc[2][NT][4];
    #pragma unroll
    for (int mt = 0; mt < 2; mt++)
        #pragma unroll
        for (int nt = 0; nt < NT; nt++)
            #pragma unroll
            for (int i = 0; i < 4; i++) acc[mt][nt][i] = 0.f;

    float4 ra[4];
    uint4 rw0, rw1;
    const int NKT = K / 32;

    #pragma unroll
    for (int j = 0; j < 4; j++) ra[j] = *(const float4*)(ap + 4 * j);
    rw0 = *(const uint4*)(wp);
    if (BN == 128) rw1 = *(const uint4*)(wp + 8);

    int cur = 0;
    {
        unsigned char* As = sm;
        unsigned char* Ws = sm + 128 * 80;
        unsigned char* da = As + arow * 80 + (akb >> 4) * 32;
        #pragma unroll
        for (int j = 0; j < 4; j++) {
            int p = pos16(4 * j) * 2;
            *(unsigned*)(da + p)     = pack_bf16(ra[j].x, ra[j].y);
            *(unsigned*)(da + p + 8) = pack_bf16(ra[j].z, ra[j].w);
        }
        unsigned char* dw = Ws + wrow * 80 + (wkb >> 4) * 32;
        if (BN == 128) {
            *(unsigned*)(dw + 0)  = rw0.x; *(unsigned*)(dw + 8)  = rw0.y;
            *(unsigned*)(dw + 16) = rw0.z; *(unsigned*)(dw + 24) = rw0.w;
            *(unsigned*)(dw + 4)  = rw1.x; *(unsigned*)(dw + 12) = rw1.y;
            *(unsigned*)(dw + 20) = rw1.z; *(unsigned*)(dw + 28) = rw1.w;
        } else {
            int b0 = (wkb & 8) ? 4 : 0;
            *(unsigned*)(dw + b0 + 0)  = rw0.x; *(unsigned*)(dw + b0 + 8)  = rw0.y;
            *(unsigned*)(dw + b0 + 16) = rw0.z; *(unsigned*)(dw + b0 + 24) = rw0.w;
        }
    }
    __syncthreads();

    for (int kt = 0; kt < NKT; kt++) {
        if (kt + 1 < NKT) {
            const int k0 = (kt + 1) * 32;
            #pragma unroll
            for (int j = 0; j < 4; j++) ra[j] = *(const float4*)(ap + k0 + 4 * j);
            rw0 = *(const uint4*)(wp + k0);
            if (BN == 128) rw1 = *(const uint4*)(wp + k0 + 8);
        }
        {
            unsigned char* As = sm + cur * (WROWS * 80);
            unsigned char* Ws = As + 128 * 80;
            #pragma unroll
            for (int kg = 0; kg < 2; kg++) {
                unsigned a[2][4];
                #pragma unroll
                for (int mt = 0; mt < 2; mt++) {
                    uint2 f0 = *(const uint2*)(As + (wm + 16 * mt + g)     * 80 + kg * 32 + t * 8);
                    uint2 f1 = *(const uint2*)(As + (wm + 16 * mt + g + 8) * 80 + kg * 32 + t * 8);
                    a[mt][0] = f0.x; a[mt][1] = f1.x; a[mt][2] = f0.y; a[mt][3] = f1.y;
                }
                #pragma unroll
                for (int nt = 0; nt < NT; nt++) {
                    uint2 b = *(const uint2*)(Ws + (wn + 8 * nt + g) * 80 + kg * 32 + t * 8);
                    mma_bf16(acc[0][nt], a[0][0], a[0][1], a[0][2], a[0][3], b.x, b.y);
                    mma_bf16(acc[1][nt], a[1][0], a[1][1], a[1][2], a[1][3], b.x, b.y);
                }
            }
        }
        if (kt + 1 < NKT) {
            unsigned char* As = sm + (cur ^ 1) * (WROWS * 80);
            unsigned char* Ws = As + 128 * 80;
            unsigned char* da = As + arow * 80 + (akb >> 4) * 32;
            #pragma unroll
            for (int j = 0; j < 4; j++) {
                int p = pos16(4 * j) * 2;
                *(unsigned*)(da + p)     = pack_bf16(ra[j].x, ra[j].y);
                *(unsigned*)(da + p + 8) = pack_bf16(ra[j].z, ra[j].w);
            }
            unsigned char* dw = Ws + wrow * 80 + (wkb >> 4) * 32;
            if (BN == 128) {
                *(unsigned*)(dw + 0)  = rw0.x; *(unsigned*)(dw + 8)  = rw0.y;
                *(unsigned*)(dw + 16) = rw0.z; *(unsigned*)(dw + 24) = rw0.w;
                *(unsigned*)(dw + 4)  = rw1.x; *(unsigned*)(dw + 12) = rw1.y;
                *(unsigned*)(dw + 20) = rw1.z; *(unsigned*)(dw + 28) = rw1.w;
            } else {
                int b0 = (wkb & 8) ? 4 : 0;
                *(unsigned*)(dw + b0 + 0)  = rw0.x; *(unsigned*)(dw + b0 + 8)  = rw0.y;
                *(unsigned*)(dw + b0 + 16) = rw0.z; *(unsigned*)(dw + b0 + 24) = rw0.w;
            }
            __syncthreads();
            cur ^= 1;
        }
    }

    #pragma unroll
    for (int mt = 0; mt < 2; mt++) {
        const int r0 = m0 + wm + 16 * mt + g;
        #pragma unroll
        for (int nt = 0; nt < NT; nt++) {
            const int n = n0 + wn + 8 * nt + 2 * t;
            #pragma unroll
            for (int half = 0; half < 2; half++) {
                const size_t ro = (size_t)(r0 + 8 * half) * ldc;
                float2 v = { acc[mt][nt][2 * half], acc[mt][nt][2 * half + 1] };
                if (bias) { v.x += bias[n]; v.y += bias[n + 1]; }
                if (OUT == 0) {
                    float* C = (float*)Cv;
                    if (EPI == 1) { v.x = fmaxf(v.x, 0.f); v.y = fmaxf(v.y, 0.f); }
                    if (EPI == 2) { v.x += res[ro + n]; v.y += res[ro + n + 1]; }
                    *(float2*)&C[ro + n] = v;
                } else {
                    __nv_bfloat16* C = (__nv_bfloat16*)Cv;
                    const float sc = (n < 512) ? 0.125f : 1.0f;
                    *(unsigned*)&C[ro + n] = pack_bf16(v.x * sc, v.y * sc);
                }
            }
        }
    }
}

// ================= fused flash attention v2: bf16 in, cp.async + ldmatrix =============
// grid (32 q-tiles, 8 heads, 2 key-splits), 128 threads (4 warps x 16 q-rows).
#define KVROW 144                     // bytes per 64-bf16 row (128 + 16 pad)
#define STG   (128 * KVROW)           // one K or V tile: 18432 B
#define ATTN_SMEM (4 * STG)           // double-buffered K+V = 73728 B

__global__ __launch_bounds__(128, 3)
void attn_fused(const __nv_bfloat16* __restrict__ qkvb, float* __restrict__ outp,
                float2* __restrict__ ml)
{
    extern __shared__ unsigned char sm[];
    const unsigned smb = (unsigned)__cvta_generic_to_shared(sm);
    const int tid = threadIdx.x;
    const int w = tid >> 5, ln = tid & 31, g = ln >> 2, t = ln & 3;
    const int h = blockIdx.y, z = blockIdx.z;
    const int q0 = blockIdx.x * 64;
    const char* qb = (const char*)qkvb;

    // ---- stage Q (already scaled by 1/8) via cp.async into stage0 K region ----
    {
        const int r = tid >> 1;
        const char* src = qb + (size_t)(q0 + r) * 3072 + h * 128 + (tid & 1) * 64;
        unsigned dst = smb + r * KVROW + (tid & 1) * 64;
        cp16(dst, src); cp16(dst + 16, src + 16);
        cp16(dst + 32, src + 32); cp16(dst + 48, src + 48);
    }
    asm volatile("cp.async.commit_group;");
    asm volatile("cp.async.wait_group 0;");
    __syncthreads();
    unsigned qa[4][4];
    {
        const unsigned qaddr = smb + (16 * w + (ln & 7) + ((ln >> 3) & 1) * 8) * KVROW
                             + (ln >> 4) * 16;
        #pragma unroll
        for (int kg = 0; kg < 4; kg++)
            ldsm_x4(qa[kg][0], qa[kg][1], qa[kg][2], qa[kg][3], qaddr + kg * 32);
    }
    __syncthreads();

    // per-thread fragment address offsets
    const unsigned koff = ((ln & 7) + ((ln >> 4) << 3)) * KVROW + ((ln >> 3) & 1) * 16;
    const unsigned voff = ((ln & 7) + ((ln >> 3) & 1) * 8) * KVROW + (ln >> 4) * 16;

    // tile issue: K rows + V rows for global key-tile ktg into buffer buf
    #define ISSUE(ktg, buf) do {                                                   \
        unsigned kd = smb + (buf) * (2 * STG) + tid * KVROW;                       \
        const char* ks = qb + (size_t)((ktg) * 128 + tid) * 3072 + 1024 + h * 128; \
        _Pragma("unroll")                                                          \
        for (int c = 0; c < 8; c++) {                                              \
            cp16(kd + c * 16, ks + c * 16);                                        \
            cp16(kd + STG + c * 16, ks + 1024 + c * 16);                           \
        }                                                                          \
        asm volatile("cp.async.commit_group;");                                    \
    } while (0)

    float m0r = -1e30f, m1r = -1e30f, l0r = 0.f, l1r = 0.f;
    float o[8][4];
    #pragma unroll
    for (int nt = 0; nt < 8; nt++)
        #pragma unroll
        for (int i = 0; i < 4; i++) o[nt][i] = 0.f;

    ISSUE(z * 8, 0);

    for (int kt = 0; kt < 8; kt++) {
        const int buf = kt & 1;
        if (kt < 7) {
            ISSUE(z * 8 + kt + 1, buf ^ 1);
            asm volatile("cp.async.wait_group 1;");
        } else {
            asm volatile("cp.async.wait_group 0;");
        }
        __syncthreads();
        const unsigned Kb = smb + buf * (2 * STG) + koff;
        const unsigned Vb = smb + buf * (2 * STG) + STG + voff;

        // ---- S = Q @ K^T ----
        float s[16][4];
        #pragma unroll
        for (int nt = 0; nt < 16; nt++)
            #pragma unroll
            for (int i = 0; i < 4; i++) s[nt][i] = 0.f;
        #pragma unroll
        for (int j = 0; j < 8; j++) {
            #pragma unroll
            for (int kg = 0; kg < 4; kg++) {
                unsigned b0, b1, b2, b3;
                ldsm_x4(b0, b1, b2, b3, Kb + j * (16 * KVROW) + kg * 32);
                mma_bf16(s[2 * j],     qa[kg][0], qa[kg][1], qa[kg][2], qa[kg][3], b0, b1);
                mma_bf16(s[2 * j + 1], qa[kg][0], qa[kg][1], qa[kg][2], qa[kg][3], b2, b3);
            }
        }

        // ---- online softmax ----
        float mx0 = -1e30f, mx1 = -1e30f;
        #pragma unroll
        for (int nt = 0; nt < 16; nt++) {
            mx0 = fmaxf(mx0, fmaxf(s[nt][0], s[nt][1]));
            mx1 = fmaxf(mx1, fmaxf(s[nt][2], s[nt][3]));
        }
        mx0 = fmaxf(mx0, __shfl_xor_sync(0xffffffffu, mx0, 1));
        mx0 = fmaxf(mx0, __shfl_xor_sync(0xffffffffu, mx0, 2));
        mx1 = fmaxf(mx1, __shfl_xor_sync(0xffffffffu, mx1, 1));
        mx1 = fmaxf(mx1, __shfl_xor_sync(0xffffffffu, mx1, 2));
        const float mn0 = fmaxf(m0r, mx0), mn1 = fmaxf(m1r, mx1);
        const float al0 = __expf(m0r - mn0), al1 = __expf(m1r - mn1);
        m0r = mn0; m1r = mn1;
        float sum0 = 0.f, sum1 = 0.f;
        #pragma unroll
        for (int nt = 0; nt < 16; nt++) {
            s[nt][0] = __expf(s[nt][0] - mn0);
            s[nt][1] = __expf(s[nt][1] - mn0);
            s[nt][2] = __expf(s[nt][2] - mn1);
            s[nt][3] = __expf(s[nt][3] - mn1);
            sum0 += s[nt][0] + s[nt][1];
            sum1 += s[nt][2] + s[nt][3];
        }
        sum0 += __shfl_xor_sync(0xffffffffu, sum0, 1);
        sum0 += __shfl_xor_sync(0xffffffffu, sum0, 2);
        sum1 += __shfl_xor_sync(0xffffffffu, sum1, 1);
        sum1 += __shfl_xor_sync(0xffffffffu, sum1, 2);
        l0r = l0r * al0 + sum0;
        l1r = l1r * al1 + sum1;
        #pragma unroll
        for (int nt = 0; nt < 8; nt++) {
            o[nt][0] *= al0; o[nt][1] *= al0;
            o[nt][2] *= al1; o[nt][3] *= al1;
        }

        // ---- O += P @ V  (P C-layout == A-layout) ----
        #pragma unroll
        for (int i = 0; i < 8; i++) {
            unsigned pa0 = pack_bf16(s[2 * i][0],     s[2 * i][1]);
            unsigned pa1 = pack_bf16(s[2 * i][2],     s[2 * i][3]);
            unsigned pa2 = pack_bf16(s[2 * i + 1][0], s[2 * i + 1][1]);
            unsigned pa3 = pack_bf16(s[2 * i + 1][2], s[2 * i + 1][3]);
            #pragma unroll
            for (int j = 0; j < 4; j++) {
                unsigned b0, b1, b2, b3;
                ldsm_x4t(b0, b1, b2, b3, Vb + i * (16 * KVROW) + j * 32);
                mma_bf16(o[2 * j],     pa0, pa1, pa2, pa3, b0, b1);
                mma_bf16(o[2 * j + 1], pa0, pa1, pa2, pa3, b2, b3);
            }
        }
        __syncthreads();
    }
    #undef ISSUE

    // ---- write unnormalized partials + (m, l) ----
    float* op = outp + (size_t)z * (B_ * D_);
    #pragma unroll
    for (int nt = 0; nt < 8; nt++) {
        const int n = h * 64 + 8 * nt + 2 * t;
        const size_t r0 = (size_t)(q0 + 16 * w + g) * D_;
        const size_t r1 = (size_t)(q0 + 16 * w + g + 8) * D_;
        *(float2*)&op[r0 + n] = make_float2(o[nt][0], o[nt][1]);
        *(float2*)&op[r1 + n] = make_float2(o[nt][2], o[nt][3]);
    }
    if (t == 0) {
        ml[((size_t)z * B_ + q0 + 16 * w + g)     * H_ + h] = make_float2(m0r, l0r);
        ml[((size_t)z * B_ + q0 + 16 * w + g + 8) * H_ + h] = make_float2(m1r, l1r);
    }
}

// ---------------- combine the two key-split partials ----------------
__global__ __launch_bounds__(256)
void attn_combine(const float* __restrict__ outp, const float2* __restrict__ ml,
                  float* __restrict__ ctx)
{
    const int token = blockIdx.x;
    const int d = threadIdx.x * 2;
    const int h = d >> 6;
    float2 p1 = ml[(size_t)token * H_ + h];
    float2 p2 = ml[((size_t)B_ + token) * H_ + h];
    float m = fmaxf(p1.x, p2.x);
    float w1 = __expf(p1.x - m), w2 = __expf(p2.x - m);
    float inv = 1.0f / (p1.y * w1 + p2.y * w2);
    float2 o1 = *(const float2*)&outp[(size_t)token * D_ + d];
    float2 o2 = *(const float2*)&outp[(size_t)(B_ + token) * D_ + d];
    float2 r = { (o1.x * w1 + o2.x * w2) * inv, (o1.y * w1 + o2.y * w2) * inv };
    *(float2*)&ctx[(size_t)token * D_ + d] = r;
}

// ---------------- per-row normalize (LN if AFFINE, InstanceNorm otherwise) ----------------
template<int N, bool AFFINE, bool ADD>
__global__ __launch_bounds__(128)
void rownorm(const float* __restrict__ src, const float* __restrict__ addv,
             const float* __restrict__ w, const float* __restrict__ bb,
             float* __restrict__ dst, float* __restrict__ dst2)
{
    constexpr int NPT = N / 128;
    const size_t base = (size_t)blockIdx.x * N;
    const int t = threadIdx.x;
    float v[NPT];
    float s = 0.f;
    #pragma unroll
    for (int i = 0; i < NPT; i++) { v[i] = src[base + t + i * 128]; s += v[i]; }
    __shared__ float sm[4];
    #pragma unroll
    for (int o = 16; o > 0; o >>= 1) s += __shfl_xor_sync(0xffffffffu, s, o);
    if ((t & 31) == 0) sm[t >> 5] = s;
    __syncthreads();
    s = sm[0] + sm[1] + sm[2] + sm[3];
    const float mean = s * (1.0f / N);
    float q = 0.f;
    #pragma unroll
    for (int i = 0; i < NPT; i++) { float d = v[i] - mean; q += d * d; }
    __syncthreads();
    #pragma unroll
    for (int o = 16; o > 0; o >>= 1) q += __shfl_xor_sync(0xffffffffu, q, o);
    if ((t & 31) == 0) sm[t >> 5] = q;
    __syncthreads();
    q = sm[0] + sm[1] + sm[2] + sm[3];
    const float r = rsqrtf(q * (1.0f / N) + EPSF);
    #pragma unroll
    for (int i = 0; i < NPT; i++) {
        int c = t + i * 128;
        float y = (v[i] - mean) * r;
        if (AFFINE) y = y * w[c] + bb[c];
        if (ADD)    y += addv[base + c];
        dst[base + c] = y;
        if (dst2) dst2[base + c] = y;
    }
}

// ---------------- cdist to prototypes, min over P, logits ----------------
__global__ __launch_bounds__(128)
void cdist_logits(const float* __restrict__ z, const float* __restrict__ hi,
                  const float* __restrict__ neg, float* __restrict__ out)
{
    __shared__ float zr[Q_];
    __shared__ float dist[128];
    const int b = blockIdx.x, t = threadIdx.x;
    zr[t] = z[(size_t)b * Q_ + t];
    dist[t] = 3.4e38f;
    __syncthreads();
    if (t < P_) {
        const float* p = hi + (size_t)t * Q_;
        float s = 0.f;
        #pragma unroll 8
        for (int d = 0; d < Q_; d++) { float df = zr[d] - p[d]; s = fmaf(df, df, s); }
        dist[t] = sqrtf(s);
    } else if (t >= 64 && t < 64 + P_) {
        const float* p = neg + (size_t)(t - 64) * Q_;
        float s = 0.f;
        #pragma unroll 8
        for (int d = 0; d < Q_; d++) { float df = zr[d] - p[d]; s = fmaf(df, df, s); }
        dist[t] = sqrtf(s);
    }
    __syncthreads();
    if (t == 0) {
        float m = 3.4e38f;
        for (int i = 0; i < P_; i++) m = fminf(m, dist[i]);
        out[b * 2 + 1] = -m;
    }
    if (t == 32) {
        float m = 3.4e38f;
        for (int i = 0; i < P_; i++) m = fminf(m, dist[64 + i]);
        out[b * 2 + 0] = -m;
    }
}

// ---------------- host driver ----------------
extern "C" void kernel_launch(void* const* d_in, const int* in_sizes, int n_in,
                              void* d_out, int out_size)
{
    const float* x        = (const float*)d_in[0];
    const float* reduce_w = (const float*)d_in[1];
    const float* reduce_b = (const float*)d_in[2];
    const float* in_w     = (const float*)d_in[3];
    const float* in_b     = (const float*)d_in[4];
    const float* out_w    = (const float*)d_in[5];
    const float* out_b    = (const float*)d_in[6];
    const float* ff1_w    = (const float*)d_in[7];
    const float* ff1_b    = (const float*)d_in[8];
    const float* ff2_w    = (const float*)d_in[9];
    const float* ff2_b    = (const float*)d_in[10];
    const float* ln1_w    = (const float*)d_in[11];
    const float* ln1_b    = (const float*)d_in[12];
    const float* ln2_w    = (const float*)d_in[13];
    const float* ln2_b    = (const float*)d_in[14];
    const float* mlp_w1   = (const float*)d_in[15];
    const float* mlp_b1   = (const float*)d_in[16];
    const float* mlp_w2   = (const float*)d_in[17];
    const float* mlp_b2   = (const float*)d_in[18];
    const float* mlp_w3   = (const float*)d_in[19];
    const float* mlp_b3   = (const float*)d_in[20];
    const float* highlights = (const float*)d_in[21];
    const float* negatives  = (const float*)d_in[22];
    float* out = (float*)d_out;

    float *feat0, *feat, *buf1, *buf2, *part, *z;
    float2* ml;
    __nv_bfloat16 *wbf, *qkvb;
    cudaGetSymbolAddress((void**)&feat0, g_feat0);
    cudaGetSymbolAddress((void**)&feat,  g_feat);
    cudaGetSymbolAddress((void**)&buf1,  g_buf1);
    cudaGetSymbolAddress((void**)&buf2,  g_buf2);
    cudaGetSymbolAddress((void**)&qkvb,  g_qkvb);
    cudaGetSymbolAddress((void**)&part,  g_part);
    cudaGetSymbolAddress((void**)&ml,    g_ml);
    cudaGetSymbolAddress((void**)&z,     g_z);
    cudaGetSymbolAddress((void**)&wbf,   g_wbf);

    cudaFuncSetAttribute(attn_fused, cudaFuncAttributeMaxDynamicSharedMemorySize,
                         ATTN_SMEM);

    // ---- convert all weights to bf16 ----
    #define CVT(src, off, n) cvt_bf16<<<((n) / 4 + 255) / 256, 256>>>(src, wbf + (off), (n) / 4)
    CVT(reduce_w, OFF_RED, D_ * DIN_);
    CVT(in_w,     OFF_IN,  L_ * 3 * D_ * D_);
    CVT(out_w,    OFF_OUT, L_ * D_ * D_);
    CVT(ff1_w,    OFF_FF1, L_ * D_ * D_);
    CVT(ff2_w,    OFF_FF2, L_ * D_ * D_);
    CVT(mlp_w1,   OFF_M1,  D_ * D_);
    CVT(mlp_w2,   OFF_M2,  D_ * D_);
    CVT(mlp_w3,   OFF_M3,  Q_ * D_);
    #undef CVT

    const dim3 blk(256);

    // feat0 = inorm(x @ reduce_w^T + b);  feat = feat0
    gemm_bf16_tn<64, 0, 0><<<dim3(D_ / 64, B_ / 128), blk>>>(
        x, wbf + OFF_RED, reduce_b, nullptr, buf1, DIN_, D_);
    rownorm<D_, false, false><<<B_, 128>>>(buf1, nullptr, nullptr, nullptr, feat0, feat);

    for (int l = 0; l < L_; l++) {
        // qkv (bf16 out, q scaled by 1/8)
        gemm_bf16_tn<128, 0, 1><<<dim3(3 * D_ / 128, B_ / 128), blk>>>(
            feat, wbf + OFF_IN + (size_t)l * 3 * D_ * D_, in_b + l * 3 * D_, nullptr,
            qkvb, D_, 3 * D_);
        attn_fused<<<dim3(B_ / 64, H_, 2), 128, ATTN_SMEM>>>(qkvb, part, ml);
        attn_combine<<<B_, 256>>>(part, ml, buf2);
        gemm_bf16_tn<64, 2, 0><<<dim3(D_ / 64, B_ / 128), blk>>>(
            buf2, wbf + OFF_OUT + (size_t)l * D_ * D_, out_b + l * D_, feat, buf1, D_, D_);
        rownorm<D_, true, false><<<B_, 128>>>(buf1, nullptr, ln1_w + l * D_, ln1_b + l * D_, feat, nullptr);
        gemm_bf16_tn<64, 1, 0><<<dim3(D_ / 64, B_ / 128), blk>>>(
            feat, wbf + OFF_FF1 + (size_t)l * D_ * D_, ff1_b + l * D_, nullptr, buf2, D_, D_);
        gemm_bf16_tn<64, 2, 0><<<dim3(D_ / 64, B_ / 128), blk>>>(
            buf2, wbf + OFF_FF2 + (size_t)l * D_ * D_, ff2_b + l * D_, feat, buf1, D_, D_);
        rownorm<D_, true, false><<<B_, 128>>>(buf1, nullptr, ln2_w + l * D_, ln2_b + l * D_, feat, nullptr);
    }

    // feat = feat0 + inorm(feat)  -> buf1
    rownorm<D_, false, true><<<B_, 128>>>(feat, feat0, nullptr, nullptr, buf1, nullptr);

    // MLP: 512 -> 512 -> 512 -> 128
    gemm_bf16_tn<64, 1, 0><<<dim3(D_ / 64, B_ / 128), blk>>>(
        buf1, wbf + OFF_M1, mlp_b1, nullptr, buf2, D_, D_);
    gemm_bf16_tn<64, 1, 0><<<dim3(D_ / 64, B_ / 128), blk>>>(
        buf2, wbf + OFF_M2, mlp_b2, nullptr, buf1, D_, D_);
    gemm_bf16_tn<64, 0, 0><<<dim3(Q_ / 64, B_ / 128), blk>>>(
        buf1, wbf + OFF_M3, mlp_b3, nullptr, buf2, D_, Q_);
    rownorm<Q_, false, false><<<B_, 128>>>(buf2, nullptr, nullptr, nullptr, z, nullptr);

    cdist_logits<<<B_, 128>>>(z, highlights, negatives, out);
}

// round 8
// speedup vs baseline: 2.0422x; 1.2415x over previous
#include <cuda_runtime.h>
#include <cuda_bf16.h>
#include <math.h>

#define B_   2048
#define DIN_ 768
#define D_   512
#define H_   8
#define HD_  64
#define L_   3
#define P_   40
#define Q_   128
#define EPSF 1e-5f

// ---------------- scratch (device globals; no allocation allowed) ----------------
__device__ float g_feat0[B_ * D_];
__device__ float g_feat [B_ * D_];
__device__ float g_buf1 [B_ * D_];
__device__ float g_buf2 [B_ * D_];
__device__ __nv_bfloat16 g_qkvb[B_ * 3 * D_];   // bf16 qkv (q pre-scaled by 1/8)
__device__ __nv_bfloat16 g_xb  [B_ * DIN_];     // bf16 copy of x
__device__ __nv_bfloat16 g_ab1 [B_ * D_];       // featb
__device__ __nv_bfloat16 g_ab2 [B_ * D_];       // ff / mlp intermediates
__device__ __nv_bfloat16 g_ab3 [B_ * D_];       // ctxb / mlp
__device__ float g_part [2 * B_ * D_];           // key-split unnormalized O partials
__device__ float2 g_ml  [2 * B_ * H_];           // key-split (m, l) per row/head
__device__ float g_z    [B_ * Q_];
__device__ __nv_bfloat16 g_wbf[5800000];         // bf16 weight pool

// weight pool offsets (elements)
#define OFF_RED  0
#define OFF_IN   (OFF_RED + D_ * DIN_)
#define OFF_OUT  (OFF_IN + L_ * 3 * D_ * D_)
#define OFF_FF1  (OFF_OUT + L_ * D_ * D_)
#define OFF_FF2  (OFF_FF1 + L_ * D_ * D_)
#define OFF_M1   (OFF_FF2 + L_ * D_ * D_)
#define OFF_M2   (OFF_M1 + D_ * D_)
#define OFF_M3   (OFF_M2 + D_ * D_)

// ---------------- helpers ----------------
__device__ __forceinline__ void mma_bf16(float* c, unsigned a0, unsigned a1,
                                         unsigned a2, unsigned a3,
                                         unsigned b0, unsigned b1) {
    asm volatile(
        "mma.sync.aligned.m16n8k16.row.col.f32.bf16.bf16.f32 "
        "{%0,%1,%2,%3}, {%4,%5,%6,%7}, {%8,%9}, {%0,%1,%2,%3};"
        : "+f"(c[0]), "+f"(c[1]), "+f"(c[2]), "+f"(c[3])
        : "r"(a0), "r"(a1), "r"(a2), "r"(a3), "r"(b0), "r"(b1));
}
__device__ __forceinline__ unsigned pack_bf16(float lo, float hi) {
    unsigned r; asm("cvt.rn.bf16x2.f32 %0, %1, %2;" : "=r"(r) : "f"(hi), "f"(lo));
    return r;
}
__device__ __forceinline__ void ldsm_x4(unsigned& a, unsigned& b, unsigned& c,
                                        unsigned& d, unsigned p) {
    asm volatile("ldmatrix.sync.aligned.m8n8.x4.shared.b16 {%0,%1,%2,%3}, [%4];"
                 : "=r"(a), "=r"(b), "=r"(c), "=r"(d) : "r"(p));
}
__device__ __forceinline__ void ldsm_x4t(unsigned& a, unsigned& b, unsigned& c,
                                         unsigned& d, unsigned p) {
    asm volatile("ldmatrix.sync.aligned.m8n8.x4.trans.shared.b16 {%0,%1,%2,%3}, [%4];"
                 : "=r"(a), "=r"(b), "=r"(c), "=r"(d) : "r"(p));
}
__device__ __forceinline__ void cp16(unsigned dst, const void* src) {
    asm volatile("cp.async.cg.shared.global [%0], [%1], 16;" :: "r"(dst), "l"(src));
}

// ---------------- fp32 -> bf16 conversion ----------------
__global__ __launch_bounds__(256)
void cvt_bf16(const float* __restrict__ in, __nv_bfloat16* __restrict__ out, int n4)
{
    int i = blockIdx.x * 256 + threadIdx.x;
    if (i < n4) {
        float4 v = ((const float4*)in)[i];
        uint2 r;
        r.x = pack_bf16(v.x, v.y);
        r.y = pack_bf16(v.z, v.w);
        ((uint2*)out)[i] = r;
    }
}

// ============ bf16 MMA GEMM v2 (cp.async + ldmatrix, double-buffered) ============
// A:[M,K] bf16, W:[N,K] bf16, C:[M,N]. BM=128, BK=32.
// EPI: 0 = bias, 1 = bias+relu, 2 = bias+residual(fp32)
// OUT: 0 = fp32 ; 1 = bf16 with cols<512 scaled by 0.125 (qkv) ; 2 = bf16
template<int BN, int EPI, int OUT>
__global__ __launch_bounds__(256)
void gemm_bf16(const __nv_bfloat16* __restrict__ A, const __nv_bfloat16* __restrict__ W,
               const float* __restrict__ bias, const float* __restrict__ res,
               void* __restrict__ Cv, int K, int ldc)
{
    constexpr int NT = BN / 16;              // n8 tiles per warp
    constexpr int TROWS = 128 + BN;
    __shared__ unsigned char sm[2 * TROWS * 80];
    const unsigned smb = (unsigned)__cvta_generic_to_shared(sm);

    const int tid = threadIdx.x;
    const int w = tid >> 5, ln = tid & 31, g = ln >> 2, t = ln & 3;
    const int wm = (w >> 1) * 32, wn = (w & 1) * (BN / 2);
    const int m0 = blockIdx.y * 128, n0 = blockIdx.x * BN;

    // staging assignments
    const int arow = tid >> 1, aoff = (tid & 1) * 32;
    const char* ap = (const char*)(A + (size_t)(m0 + arow) * K) + aoff;
    const int wrow = (BN == 128) ? (tid >> 1) : (tid >> 2);
    const int woff = (BN == 128) ? ((tid & 1) * 32) : ((tid & 3) * 16);
    const char* wp = (const char*)(W + (size_t)(n0 + wrow) * K) + woff;

    // fragment addresses (within a buffer)
    const unsigned aAddr = (wm + (ln & 7) + ((ln >> 3) & 1) * 8) * 80 + (ln >> 4) * 16;
    const unsigned wAddr = 128 * 80 + (wn + (ln & 7) + (ln >> 4) * 8) * 80
                         + ((ln >> 3) & 1) * 16;

    float acc[2][NT][4];
    #pragma unroll
    for (int mt = 0; mt < 2; mt++)
        #pragma unroll
        for (int nt = 0; nt < NT; nt++)
            #pragma unroll
            for (int i = 0; i < 4; i++) acc[mt][nt][i] = 0.f;

    const int NKT = K / 32;

    #define GISSUE(kt, buf) do {                                             \
        unsigned ad = smb + (buf) * (TROWS * 80) + arow * 80 + aoff;         \
        cp16(ad, ap + (size_t)(kt) * 64);                                    \
        cp16(ad + 16, ap + (size_t)(kt) * 64 + 16);                          \
        unsigned wd = smb + (buf) * (TROWS * 80) + 128 * 80 + wrow * 80 + woff; \
        cp16(wd, wp + (size_t)(kt) * 64);                                    \
        if (BN == 128) cp16(wd + 16, wp + (size_t)(kt) * 64 + 16);           \
        asm volatile("cp.async.commit_group;");                              \
    } while (0)

    GISSUE(0, 0);

    for (int kt = 0; kt < NKT; kt++) {
        const int buf = kt & 1;
        if (kt + 1 < NKT) {
            GISSUE(kt + 1, buf ^ 1);
            asm volatile("cp.async.wait_group 1;");
        } else {
            asm volatile("cp.async.wait_group 0;");
        }
        __syncthreads();
        const unsigned base = smb + buf * (TROWS * 80);
        #pragma unroll
        for (int kg = 0; kg < 2; kg++) {
            unsigned a[2][4];
            ldsm_x4(a[0][0], a[0][1], a[0][2], a[0][3], base + aAddr + kg * 32);
            ldsm_x4(a[1][0], a[1][1], a[1][2], a[1][3], base + aAddr + 16 * 80 + kg * 32);
            #pragma unroll
            for (int ng = 0; ng < NT / 2; ng++) {
                unsigned b0, b1, b2, b3;
                ldsm_x4(b0, b1, b2, b3, base + wAddr + ng * (16 * 80) + kg * 32);
                mma_bf16(acc[0][2 * ng],     a[0][0], a[0][1], a[0][2], a[0][3], b0, b1);
                mma_bf16(acc[0][2 * ng + 1], a[0][0], a[0][1], a[0][2], a[0][3], b2, b3);
                mma_bf16(acc[1][2 * ng],     a[1][0], a[1][1], a[1][2], a[1][3], b0, b1);
                mma_bf16(acc[1][2 * ng + 1], a[1][0], a[1][1], a[1][2], a[1][3], b2, b3);
            }
        }
        __syncthreads();
    }
    #undef GISSUE

    #pragma unroll
    for (int mt = 0; mt < 2; mt++) {
        const int r0 = m0 + wm + 16 * mt + g;
        #pragma unroll
        for (int nt = 0; nt < NT; nt++) {
            const int n = n0 + wn + 8 * nt + 2 * t;
            #pragma unroll
            for (int half = 0; half < 2; half++) {
                const size_t ro = (size_t)(r0 + 8 * half) * ldc;
                float2 v = { acc[mt][nt][2 * half], acc[mt][nt][2 * half + 1] };
                if (bias) { v.x += bias[n]; v.y += bias[n + 1]; }
                if (EPI == 1) { v.x = fmaxf(v.x, 0.f); v.y = fmaxf(v.y, 0.f); }
                if (EPI == 2) { v.x += res[ro + n]; v.y += res[ro + n + 1]; }
                if (OUT == 0) {
                    *(float2*)&((float*)Cv)[ro + n] = v;
                } else if (OUT == 1) {
                    const float sc = (n < 512) ? 0.125f : 1.0f;
                    *(unsigned*)&((__nv_bfloat16*)Cv)[ro + n] = pack_bf16(v.x * sc, v.y * sc);
                } else {
                    *(unsigned*)&((__nv_bfloat16*)Cv)[ro + n] = pack_bf16(v.x, v.y);
                }
            }
        }
    }
}

// ================= fused flash attention: bf16 in, cp.async + ldmatrix =============
#define KVROW 144
#define STG   (128 * KVROW)
#define ATTN_SMEM (4 * STG)

__global__ __launch_bounds__(128, 3)
void attn_fused(const __nv_bfloat16* __restrict__ qkvb, float* __restrict__ outp,
                float2* __restrict__ ml)
{
    extern __shared__ unsigned char sm[];
    const unsigned smb = (unsigned)__cvta_generic_to_shared(sm);
    const int tid = threadIdx.x;
    const int w = tid >> 5, ln = tid & 31, g = ln >> 2, t = ln & 3;
    const int h = blockIdx.y, z = blockIdx.z;
    const int q0 = blockIdx.x * 64;
    const char* qb = (const char*)qkvb;

    {
        const int r = tid >> 1;
        const char* src = qb + (size_t)(q0 + r) * 3072 + h * 128 + (tid & 1) * 64;
        unsigned dst = smb + r * KVROW + (tid & 1) * 64;
        cp16(dst, src); cp16(dst + 16, src + 16);
        cp16(dst + 32, src + 32); cp16(dst + 48, src + 48);
    }
    asm volatile("cp.async.commit_group;");
    asm volatile("cp.async.wait_group 0;");
    __syncthreads();
    unsigned qa[4][4];
    {
        const unsigned qaddr = smb + (16 * w + (ln & 7) + ((ln >> 3) & 1) * 8) * KVROW
                             + (ln >> 4) * 16;
        #pragma unroll
        for (int kg = 0; kg < 4; kg++)
            ldsm_x4(qa[kg][0], qa[kg][1], qa[kg][2], qa[kg][3], qaddr + kg * 32);
    }
    __syncthreads();

    const unsigned koff = ((ln & 7) + ((ln >> 4) << 3)) * KVROW + ((ln >> 3) & 1) * 16;
    const unsigned voff = ((ln & 7) + ((ln >> 3) & 1) * 8) * KVROW + (ln >> 4) * 16;

    #define ISSUE(ktg, buf) do {                                                   \
        unsigned kd = smb + (buf) * (2 * STG) + tid * KVROW;                       \
        const char* ks = qb + (size_t)((ktg) * 128 + tid) * 3072 + 1024 + h * 128; \
        _Pragma("unroll")                                                          \
        for (int c = 0; c < 8; c++) {                                              \
            cp16(kd + c * 16, ks + c * 16);                                        \
            cp16(kd + STG + c * 16, ks + 1024 + c * 16);                           \
        }                                                                          \
        asm volatile("cp.async.commit_group;");                                    \
    } while (0)

    float m0r = -1e30f, m1r = -1e30f, l0r = 0.f, l1r = 0.f;
    float o[8][4];
    #pragma unroll
    for (int nt = 0; nt < 8; nt++)
        #pragma unroll
        for (int i = 0; i < 4; i++) o[nt][i] = 0.f;

    ISSUE(z * 8, 0);

    for (int kt = 0; kt < 8; kt++) {
        const int buf = kt & 1;
        if (kt < 7) {
            ISSUE(z * 8 + kt + 1, buf ^ 1);
            asm volatile("cp.async.wait_group 1;");
        } else {
            asm volatile("cp.async.wait_group 0;");
        }
        __syncthreads();
        const unsigned Kb = smb + buf * (2 * STG) + koff;
        const unsigned Vb = smb + buf * (2 * STG) + STG + voff;

        float s[16][4];
        #pragma unroll
        for (int nt = 0; nt < 16; nt++)
            #pragma unroll
            for (int i = 0; i < 4; i++) s[nt][i] = 0.f;
        #pragma unroll
        for (int j = 0; j < 8; j++) {
            #pragma unroll
            for (int kg = 0; kg < 4; kg++) {
                unsigned b0, b1, b2, b3;
                ldsm_x4(b0, b1, b2, b3, Kb + j * (16 * KVROW) + kg * 32);
                mma_bf16(s[2 * j],     qa[kg][0], qa[kg][1], qa[kg][2], qa[kg][3], b0, b1);
                mma_bf16(s[2 * j + 1], qa[kg][0], qa[kg][1], qa[kg][2], qa[kg][3], b2, b3);
            }
        }

        float mx0 = -1e30f, mx1 = -1e30f;
        #pragma unroll
        for (int nt = 0; nt < 16; nt++) {
            mx0 = fmaxf(mx0, fmaxf(s[nt][0], s[nt][1]));
            mx1 = fmaxf(mx1, fmaxf(s[nt][2], s[nt][3]));
        }
        mx0 = fmaxf(mx0, __shfl_xor_sync(0xffffffffu, mx0, 1));
        mx0 = fmaxf(mx0, __shfl_xor_sync(0xffffffffu, mx0, 2));
        mx1 = fmaxf(mx1, __shfl_xor_sync(0xffffffffu, mx1, 1));
        mx1 = fmaxf(mx1, __shfl_xor_sync(0xffffffffu, mx1, 2));
        const float mn0 = fmaxf(m0r, mx0), mn1 = fmaxf(m1r, mx1);
        const float al0 = __expf(m0r - mn0), al1 = __expf(m1r - mn1);
        m0r = mn0; m1r = mn1;
        float sum0 = 0.f, sum1 = 0.f;
        #pragma unroll
        for (int nt = 0; nt < 16; nt++) {
            s[nt][0] = __expf(s[nt][0] - mn0);
            s[nt][1] = __expf(s[nt][1] - mn0);
            s[nt][2] = __expf(s[nt][2] - mn1);
            s[nt][3] = __expf(s[nt][3] - mn1);
            sum0 += s[nt][0] + s[nt][1];
            sum1 += s[nt][2] + s[nt][3];
        }
        sum0 += __shfl_xor_sync(0xffffffffu, sum0, 1);
        sum0 += __shfl_xor_sync(0xffffffffu, sum0, 2);
        sum1 += __shfl_xor_sync(0xffffffffu, sum1, 1);
        sum1 += __shfl_xor_sync(0xffffffffu, sum1, 2);
        l0r = l0r * al0 + sum0;
        l1r = l1r * al1 + sum1;
        #pragma unroll
        for (int nt = 0; nt < 8; nt++) {
            o[nt][0] *= al0; o[nt][1] *= al0;
            o[nt][2] *= al1; o[nt][3] *= al1;
        }

        #pragma unroll
        for (int i = 0; i < 8; i++) {
            unsigned pa0 = pack_bf16(s[2 * i][0],     s[2 * i][1]);
            unsigned pa1 = pack_bf16(s[2 * i][2],     s[2 * i][3]);
            unsigned pa2 = pack_bf16(s[2 * i + 1][0], s[2 * i + 1][1]);
            unsigned pa3 = pack_bf16(s[2 * i + 1][2], s[2 * i + 1][3]);
            #pragma unroll
            for (int j = 0; j < 4; j++) {
                unsigned b0, b1, b2, b3;
                ldsm_x4t(b0, b1, b2, b3, Vb + i * (16 * KVROW) + j * 32);
                mma_bf16(o[2 * j],     pa0, pa1, pa2, pa3, b0, b1);
                mma_bf16(o[2 * j + 1], pa0, pa1, pa2, pa3, b2, b3);
            }
        }
        __syncthreads();
    }
    #undef ISSUE

    float* op = outp + (size_t)z * (B_ * D_);
    #pragma unroll
    for (int nt = 0; nt < 8; nt++) {
        const int n = h * 64 + 8 * nt + 2 * t;
        const size_t r0 = (size_t)(q0 + 16 * w + g) * D_;
        const size_t r1 = (size_t)(q0 + 16 * w + g + 8) * D_;
        *(float2*)&op[r0 + n] = make_float2(o[nt][0], o[nt][1]);
        *(float2*)&op[r1 + n] = make_float2(o[nt][2], o[nt][3]);
    }
    if (t == 0) {
        ml[((size_t)z * B_ + q0 + 16 * w + g)     * H_ + h] = make_float2(m0r, l0r);
        ml[((size_t)z * B_ + q0 + 16 * w + g + 8) * H_ + h] = make_float2(m1r, l1r);
    }
}

// ---------------- combine key-split partials -> bf16 ctx ----------------
__global__ __launch_bounds__(256)
void attn_combine(const float* __restrict__ outp, const float2* __restrict__ ml,
                  __nv_bfloat16* __restrict__ ctxb)
{
    const int token = blockIdx.x;
    const int d = threadIdx.x * 2;
    const int h = d >> 6;
    float2 p1 = ml[(size_t)token * H_ + h];
    float2 p2 = ml[((size_t)B_ + token) * H_ + h];
    float m = fmaxf(p1.x, p2.x);
    float w1 = __expf(p1.x - m), w2 = __expf(p2.x - m);
    float inv = 1.0f / (p1.y * w1 + p2.y * w2);
    float2 o1 = *(const float2*)&outp[(size_t)token * D_ + d];
    float2 o2 = *(const float2*)&outp[(size_t)(B_ + token) * D_ + d];
    float rx = (o1.x * w1 + o2.x * w2) * inv;
    float ry = (o1.y * w1 + o2.y * w2) * inv;
    *(unsigned*)&ctxb[(size_t)token * D_ + d] = pack_bf16(rx, ry);
}

// ---------------- per-row normalize (fp32 dst optional, bf16 dstb optional) ----------------
template<int N, bool AFFINE, bool ADD>
__global__ __launch_bounds__(128)
void rownorm(const float* __restrict__ src, const float* __restrict__ addv,
             const float* __restrict__ w, const float* __restrict__ bb,
             float* __restrict__ dst, __nv_bfloat16* __restrict__ dstb)
{
    constexpr int NPT = N / 128;
    const size_t base = (size_t)blockIdx.x * N;
    const int t = threadIdx.x;
    float v[NPT];
    float s = 0.f;
    #pragma unroll
    for (int i = 0; i < NPT; i++) { v[i] = src[base + t + i * 128]; s += v[i]; }
    __shared__ float sm[4];
    #pragma unroll
    for (int o = 16; o > 0; o >>= 1) s += __shfl_xor_sync(0xffffffffu, s, o);
    if ((t & 31) == 0) sm[t >> 5] = s;
    __syncthreads();
    s = sm[0] + sm[1] + sm[2] + sm[3];
    const float mean = s * (1.0f / N);
    float q = 0.f;
    #pragma unroll
    for (int i = 0; i < NPT; i++) { float d = v[i] - mean; q += d * d; }
    __syncthreads();
    #pragma unroll
    for (int o = 16; o > 0; o >>= 1) q += __shfl_xor_sync(0xffffffffu, q, o);
    if ((t & 31) == 0) sm[t >> 5] = q;
    __syncthreads();
    q = sm[0] + sm[1] + sm[2] + sm[3];
    const float r = rsqrtf(q * (1.0f / N) + EPSF);
    #pragma unroll
    for (int i = 0; i < NPT; i++) {
        int c = t + i * 128;
        float y = (v[i] - mean) * r;
        if (AFFINE) y = y * w[c] + bb[c];
        if (ADD)    y += addv[base + c];
        if (dst)  dst[base + c] = y;
        if (dstb) dstb[base + c] = __float2bfloat16(y);
    }
}

// ---------------- cdist to prototypes, min over P, logits ----------------
__global__ __launch_bounds__(128)
void cdist_logits(const float* __restrict__ z, const float* __restrict__ hi,
                  const float* __restrict__ neg, float* __restrict__ out)
{
    __shared__ float zr[Q_];
    __shared__ float dist[128];
    const int b = blockIdx.x, t = threadIdx.x;
    zr[t] = z[(size_t)b * Q_ + t];
    dist[t] = 3.4e38f;
    __syncthreads();
    if (t < P_) {
        const float* p = hi + (size_t)t * Q_;
        float s = 0.f;
        #pragma unroll 8
        for (int d = 0; d < Q_; d++) { float df = zr[d] - p[d]; s = fmaf(df, df, s); }
        dist[t] = sqrtf(s);
    } else if (t >= 64 && t < 64 + P_) {
        const float* p = neg + (size_t)(t - 64) * Q_;
        float s = 0.f;
        #pragma unroll 8
        for (int d = 0; d < Q_; d++) { float df = zr[d] - p[d]; s = fmaf(df, df, s); }
        dist[t] = sqrtf(s);
    }
    __syncthreads();
    if (t == 0) {
        float m = 3.4e38f;
        for (int i = 0; i < P_; i++) m = fminf(m, dist[i]);
        out[b * 2 + 1] = -m;
    }
    if (t == 32) {
        float m = 3.4e38f;
        for (int i = 0; i < P_; i++) m = fminf(m, dist[64 + i]);
        out[b * 2 + 0] = -m;
    }
}

// ---------------- host driver ----------------
extern "C" void kernel_launch(void* const* d_in, const int* in_sizes, int n_in,
                              void* d_out, int out_size)
{
    const float* x        = (const float*)d_in[0];
    const float* reduce_w = (const float*)d_in[1];
    const float* reduce_b = (const float*)d_in[2];
    const float* in_w     = (const float*)d_in[3];
    const float* in_b     = (const float*)d_in[4];
    const float* out_w    = (const float*)d_in[5];
    const float* out_b    = (const float*)d_in[6];
    const float* ff1_w    = (const float*)d_in[7];
    const float* ff1_b    = (const float*)d_in[8];
    const float* ff2_w    = (const float*)d_in[9];
    const float* ff2_b    = (const float*)d_in[10];
    const float* ln1_w    = (const float*)d_in[11];
    const float* ln1_b    = (const float*)d_in[12];
    const float* ln2_w    = (const float*)d_in[13];
    const float* ln2_b    = (const float*)d_in[14];
    const float* mlp_w1   = (const float*)d_in[15];
    const float* mlp_b1   = (const float*)d_in[16];
    const float* mlp_w2   = (const float*)d_in[17];
    const float* mlp_b2   = (const float*)d_in[18];
    const float* mlp_w3   = (const float*)d_in[19];
    const float* mlp_b3   = (const float*)d_in[20];
    const float* highlights = (const float*)d_in[21];
    const float* negatives  = (const float*)d_in[22];
    float* out = (float*)d_out;

    float *feat0, *feat, *buf1, *buf2, *part, *z;
    float2* ml;
    __nv_bfloat16 *wbf, *qkvb, *xb, *ab1, *ab2, *ab3;
    cudaGetSymbolAddress((void**)&feat0, g_feat0);
    cudaGetSymbolAddress((void**)&feat,  g_feat);
    cudaGetSymbolAddress((void**)&buf1,  g_buf1);
    cudaGetSymbolAddress((void**)&buf2,  g_buf2);
    cudaGetSymbolAddress((void**)&qkvb,  g_qkvb);
    cudaGetSymbolAddress((void**)&xb,    g_xb);
    cudaGetSymbolAddress((void**)&ab1,   g_ab1);
    cudaGetSymbolAddress((void**)&ab2,   g_ab2);
    cudaGetSymbolAddress((void**)&ab3,   g_ab3);
    cudaGetSymbolAddress((void**)&part,  g_part);
    cudaGetSymbolAddress((void**)&ml,    g_ml);
    cudaGetSymbolAddress((void**)&z,     g_z);
    cudaGetSymbolAddress((void**)&wbf,   g_wbf);

    cudaFuncSetAttribute(attn_fused, cudaFuncAttributeMaxDynamicSharedMemorySize,
                         ATTN_SMEM);

    // ---- convert all weights + x to bf16 ----
    #define CVT(src, dst, n) cvt_bf16<<<((n) / 4 + 255) / 256, 256>>>(src, dst, (n) / 4)
    CVT(reduce_w, wbf + OFF_RED, D_ * DIN_);
    CVT(in_w,     wbf + OFF_IN,  L_ * 3 * D_ * D_);
    CVT(out_w,    wbf + OFF_OUT, L_ * D_ * D_);
    CVT(ff1_w,    wbf + OFF_FF1, L_ * D_ * D_);
    CVT(ff2_w,    wbf + OFF_FF2, L_ * D_ * D_);
    CVT(mlp_w1,   wbf + OFF_M1,  D_ * D_);
    CVT(mlp_w2,   wbf + OFF_M2,  D_ * D_);
    CVT(mlp_w3,   wbf + OFF_M3,  Q_ * D_);
    CVT(x,        xb,            B_ * DIN_);
    #undef CVT

    const dim3 blk(256);

    // feat0 = inorm(x @ reduce_w^T + b)  (fp32 + bf16 copies)
    gemm_bf16<64, 0, 0><<<dim3(D_ / 64, B_ / 128), blk>>>(
        xb, wbf + OFF_RED, reduce_b, nullptr, buf1, DIN_, D_);
    rownorm<D_, false, false><<<B_, 128>>>(buf1, nullptr, nullptr, nullptr, feat0, ab1);

    const float* featPrev = feat0;
    for (int l = 0; l < L_; l++) {
        gemm_bf16<128, 0, 1><<<dim3(3 * D_ / 128, B_ / 128), blk>>>(
            ab1, wbf + OFF_IN + (size_t)l * 3 * D_ * D_, in_b + l * 3 * D_, nullptr,
            qkvb, D_, 3 * D_);
        attn_fused<<<dim3(B_ / 64, H_, 2), 128, ATTN_SMEM>>>(qkvb, part, ml);
        attn_combine<<<B_, 256>>>(part, ml, ab3);
        gemm_bf16<64, 2, 0><<<dim3(D_ / 64, B_ / 128), blk>>>(
            ab3, wbf + OFF_OUT + (size_t)l * D_ * D_, out_b + l * D_, featPrev, buf1, D_, D_);
        rownorm<D_, true, false><<<B_, 128>>>(buf1, nullptr, ln1_w + l * D_, ln1_b + l * D_,
                                              feat, ab1);
        gemm_bf16<64, 1, 2><<<dim3(D_ / 64, B_ / 128), blk>>>(
            ab1, wbf + OFF_FF1 + (size_t)l * D_ * D_, ff1_b + l * D_, nullptr, ab2, D_, D_);
        gemm_bf16<64, 2, 0><<<dim3(D_ / 64, B_ / 128), blk>>>(
            ab2, wbf + OFF_FF2 + (size_t)l * D_ * D_, ff2_b + l * D_, feat, buf1, D_, D_);
        rownorm<D_, true, false><<<B_, 128>>>(buf1, nullptr, ln2_w + l * D_, ln2_b + l * D_,
                                              feat, ab1);
        featPrev = feat;
    }

    // featb = feat0 + inorm(feat)   (bf16 only — consumed by mlp1)
    rownorm<D_, false, true><<<B_, 128>>>(feat, feat0, nullptr, nullptr, nullptr, ab1);

    // MLP: 512 -> 512 -> 512 -> 128
    gemm_bf16<64, 1, 2><<<dim3(D_ / 64, B_ / 128), blk>>>(
        ab1, wbf + OFF_M1, mlp_b1, nullptr, ab2, D_, D_);
    gemm_bf16<64, 1, 2><<<dim3(D_ / 64, B_ / 128), blk>>>(
        ab2, wbf + OFF_M2, mlp_b2, nullptr, ab3, D_, D_);
    gemm_bf16<64, 0, 0><<<dim3(Q_ / 64, B_ / 128), blk>>>(
        ab3, wbf + OFF_M3, mlp_b3, nullptr, buf2, D_, Q_);
    rownorm<Q_, false, false><<<B_, 128>>>(buf2, nullptr, nullptr, nullptr, z, nullptr);

    cdist_logits<<<B_, 128>>>(z, highlights, negatives, out);
}

// round 10
// speedup vs baseline: 2.1375x; 1.0467x over previous
#include <cuda_runtime.h>
#include <cuda_bf16.h>
#include <math.h>

#define B_   2048
#define DIN_ 768
#define D_   512
#define H_   8
#define HD_  64
#define L_   3
#define P_   40
#define Q_   128
#define EPSF 1e-5f

// ---------------- scratch (device globals; no allocation allowed) ----------------
__device__ float g_feat0[B_ * D_];
__device__ float g_feat [B_ * D_];
__device__ float g_buf1 [B_ * D_];
__device__ float g_buf2 [B_ * D_];
__device__ __nv_bfloat16 g_qkvb[B_ * 3 * D_];   // bf16 qkv (q pre-scaled by 1/8)
__device__ __nv_bfloat16 g_xb  [B_ * DIN_];     // bf16 copy of x
__device__ __nv_bfloat16 g_ab1 [B_ * D_];
__device__ __nv_bfloat16 g_ab2 [B_ * D_];
__device__ __nv_bfloat16 g_ab3 [B_ * D_];
__device__ float g_z    [B_ * Q_];
__device__ __nv_bfloat16 g_wbf[5800000];         // bf16 weight pool

#define OFF_RED  0
#define OFF_IN   (OFF_RED + D_ * DIN_)
#define OFF_OUT  (OFF_IN + L_ * 3 * D_ * D_)
#define OFF_FF1  (OFF_OUT + L_ * D_ * D_)
#define OFF_FF2  (OFF_FF1 + L_ * D_ * D_)
#define OFF_M1   (OFF_FF2 + L_ * D_ * D_)
#define OFF_M2   (OFF_M1 + D_ * D_)
#define OFF_M3   (OFF_M2 + D_ * D_)

// ---------------- helpers ----------------
__device__ __forceinline__ void mma_bf16(float* c, unsigned a0, unsigned a1,
                                         unsigned a2, unsigned a3,
                                         unsigned b0, unsigned b1) {
    asm volatile(
        "mma.sync.aligned.m16n8k16.row.col.f32.bf16.bf16.f32 "
        "{%0,%1,%2,%3}, {%4,%5,%6,%7}, {%8,%9}, {%0,%1,%2,%3};"
        : "+f"(c[0]), "+f"(c[1]), "+f"(c[2]), "+f"(c[3])
        : "r"(a0), "r"(a1), "r"(a2), "r"(a3), "r"(b0), "r"(b1));
}
__device__ __forceinline__ unsigned pack_bf16(float lo, float hi) {
    unsigned r; asm("cvt.rn.bf16x2.f32 %0, %1, %2;" : "=r"(r) : "f"(hi), "f"(lo));
    return r;
}
__device__ __forceinline__ void ldsm_x4(unsigned& a, unsigned& b, unsigned& c,
                                        unsigned& d, unsigned p) {
    asm volatile("ldmatrix.sync.aligned.m8n8.x4.shared.b16 {%0,%1,%2,%3}, [%4];"
                 : "=r"(a), "=r"(b), "=r"(c), "=r"(d) : "r"(p));
}
__device__ __forceinline__ void ldsm_x4t(unsigned& a, unsigned& b, unsigned& c,
                                         unsigned& d, unsigned p) {
    asm volatile("ldmatrix.sync.aligned.m8n8.x4.trans.shared.b16 {%0,%1,%2,%3}, [%4];"
                 : "=r"(a), "=r"(b), "=r"(c), "=r"(d) : "r"(p));
}
__device__ __forceinline__ void cp16(unsigned dst, const void* src) {
    asm volatile("cp.async.cg.shared.global [%0], [%1], 16;" :: "r"(dst), "l"(src));
}

// ---------------- merged fp32 -> bf16 conversion (9 segments, 1 launch) ----------------
struct Cvt9 {
    const float* s[9];
    __nv_bfloat16* d[9];
    int cum[10];   // cumulative float4 counts
};
__global__ __launch_bounds__(256)
void cvt_bf16_all(Cvt9 a)
{
    int gid = blockIdx.x * 256 + threadIdx.x;
    if (gid >= a.cum[9]) return;
    int seg = 0;
    #pragma unroll
    for (int i = 1; i < 9; i++) if (gid >= a.cum[i]) seg = i;
    int idx = gid - a.cum[seg];
    float4 v = ((const float4*)a.s[seg])[idx];
    uint2 r;
    r.x = pack_bf16(v.x, v.y);
    r.y = pack_bf16(v.z, v.w);
    ((uint2*)a.d[seg])[idx] = r;
}

// ============ bf16 MMA GEMM v3: 3-stage cp.async, 1 sync/tile, ldmatrix ============
// A:[M,K] bf16, W:[N,K] bf16, C:[M,N]. BM=128, BK=32, 3 stages.
// EPI: 0 = bias, 1 = bias+relu, 2 = bias+residual(fp32)
// OUT: 0 = fp32 ; 1 = bf16 with cols<512 scaled by 0.125 (qkv) ; 2 = bf16
template<int BN, int EPI, int OUT>
__global__ __launch_bounds__(256)
void gemm_bf16(const __nv_bfloat16* __restrict__ A, const __nv_bfloat16* __restrict__ W,
               const float* __restrict__ bias, const float* __restrict__ res,
               void* __restrict__ Cv, int K, int ldc)
{
    constexpr int NT = BN / 16;
    constexpr int TROWS = 128 + BN;
    constexpr unsigned SSZ = TROWS * 80;
    extern __shared__ unsigned char smx[];
    const unsigned smb = (unsigned)__cvta_generic_to_shared(smx);

    const int tid = threadIdx.x;
    const int w = tid >> 5, ln = tid & 31, g = ln >> 2, t = ln & 3;
    const int wm = (w >> 1) * 32, wn = (w & 1) * (BN / 2);
    const int m0 = blockIdx.y * 128, n0 = blockIdx.x * BN;

    const int arow = tid >> 1, aoff = (tid & 1) * 32;
    const char* ap = (const char*)(A + (size_t)(m0 + arow) * K) + aoff;
    const int wrow = (BN == 128) ? (tid >> 1) : (tid >> 2);
    const int woff = (BN == 128) ? ((tid & 1) * 32) : ((tid & 3) * 16);
    const char* wp = (const char*)(W + (size_t)(n0 + wrow) * K) + woff;

    const unsigned aAddr = (wm + (ln & 7) + ((ln >> 3) & 1) * 8) * 80 + (ln >> 4) * 16;
    const unsigned wAddr = 128 * 80 + (wn + (ln & 7) + (ln >> 4) * 8) * 80
                         + ((ln >> 3) & 1) * 16;

    float acc[2][NT][4];
    #pragma unroll
    for (int mt = 0; mt < 2; mt++)
        #pragma unroll
        for (int nt = 0; nt < NT; nt++)
            #pragma unroll
            for (int i = 0; i < 4; i++) acc[mt][nt][i] = 0.f;

    const int NKT = K / 32;

    #define GISSUE(kt, slot) do {                                            \
        unsigned ad = smb + (unsigned)(slot) * SSZ + arow * 80 + aoff;       \
        cp16(ad, ap + (size_t)(kt) * 64);                                    \
        cp16(ad + 16, ap + (size_t)(kt) * 64 + 16);                          \
        unsigned wd = smb + (unsigned)(slot) * SSZ + 128 * 80 + wrow * 80 + woff; \
        cp16(wd, wp + (size_t)(kt) * 64);                                    \
        if (BN == 128) cp16(wd + 16, wp + (size_t)(kt) * 64 + 16);           \
        asm volatile("cp.async.commit_group;");                              \
    } while (0)

    GISSUE(0, 0);
    GISSUE(1, 1);

    for (int kt = 0; kt < NKT; kt++) {
        if (kt + 1 < NKT) asm volatile("cp.async.wait_group 1;");
        else              asm volatile("cp.async.wait_group 0;");
        __syncthreads();
        if (kt + 2 < NKT) {
            int slot = kt + 2;
            slot -= (slot >= 3) ? 3 : 0;
            slot -= (slot >= 3) ? 3 : 0;   // (kt+2)%3 without div for small vals
            GISSUE(kt + 2, (kt + 2) % 3);
        }
        const unsigned base = smb + (unsigned)(kt % 3) * SSZ;
        #pragma unroll
        for (int kg = 0; kg < 2; kg++) {
            unsigned a[2][4];
            ldsm_x4(a[0][0], a[0][1], a[0][2], a[0][3], base + aAddr + kg * 32);
            ldsm_x4(a[1][0], a[1][1], a[1][2], a[1][3], base + aAddr + 16 * 80 + kg * 32);
            #pragma unroll
            for (int ng = 0; ng < NT / 2; ng++) {
                unsigned b0, b1, b2, b3;
                ldsm_x4(b0, b1, b2, b3, base + wAddr + ng * (16 * 80) + kg * 32);
                mma_bf16(acc[0][2 * ng],     a[0][0], a[0][1], a[0][2], a[0][3], b0, b1);
                mma_bf16(acc[0][2 * ng + 1], a[0][0], a[0][1], a[0][2], a[0][3], b2, b3);
                mma_bf16(acc[1][2 * ng],     a[1][0], a[1][1], a[1][2], a[1][3], b0, b1);
                mma_bf16(acc[1][2 * ng + 1], a[1][0], a[1][1], a[1][2], a[1][3], b2, b3);
            }
        }
    }
    #undef GISSUE

    #pragma unroll
    for (int mt = 0; mt < 2; mt++) {
        const int r0 = m0 + wm + 16 * mt + g;
        #pragma unroll
        for (int nt = 0; nt < NT; nt++) {
            const int n = n0 + wn + 8 * nt + 2 * t;
            #pragma unroll
            for (int half = 0; half < 2; half++) {
                const size_t ro = (size_t)(r0 + 8 * half) * ldc;
                float2 v = { acc[mt][nt][2 * half], acc[mt][nt][2 * half + 1] };
                if (bias) { v.x += bias[n]; v.y += bias[n + 1]; }
                if (EPI == 1) { v.x = fmaxf(v.x, 0.f); v.y = fmaxf(v.y, 0.f); }
                if (EPI == 2) { v.x += res[ro + n]; v.y += res[ro + n + 1]; }
                if (OUT == 0) {
                    *(float2*)&((float*)Cv)[ro + n] = v;
                } else if (OUT == 1) {
                    const float sc = (n < 512) ? 0.125f : 1.0f;
                    *(unsigned*)&((__nv_bfloat16*)Cv)[ro + n] = pack_bf16(v.x * sc, v.y * sc);
                } else {
                    *(unsigned*)&((__nv_bfloat16*)Cv)[ro + n] = pack_bf16(v.x, v.y);
                }
            }
        }
    }
}

// ================= fused flash attention (no key-split, direct bf16 out) =============
#define KVROW 144
#define STG   (128 * KVROW)
#define ATTN_SMEM (4 * STG)

__global__ __launch_bounds__(128, 3)
void attn_fused(const __nv_bfloat16* __restrict__ qkvb, __nv_bfloat16* __restrict__ ctxb)
{
    extern __shared__ unsigned char sm[];
    const unsigned smb = (unsigned)__cvta_generic_to_shared(sm);
    const int tid = threadIdx.x;
    const int w = tid >> 5, ln = tid & 31, g = ln >> 2, t = ln & 3;
    const int h = blockIdx.y;
    const int q0 = blockIdx.x * 64;
    const char* qb = (const char*)qkvb;

    {
        const int r = tid >> 1;
        const char* src = qb + (size_t)(q0 + r) * 3072 + h * 128 + (tid & 1) * 64;
        unsigned dst = smb + r * KVROW + (tid & 1) * 64;
        cp16(dst, src); cp16(dst + 16, src + 16);
        cp16(dst + 32, src + 32); cp16(dst + 48, src + 48);
    }
    asm volatile("cp.async.commit_group;");
    asm volatile("cp.async.wait_group 0;");
    __syncthreads();
    unsigned qa[4][4];
    {
        const unsigned qaddr = smb + (16 * w + (ln & 7) + ((ln >> 3) & 1) * 8) * KVROW
                             + (ln >> 4) * 16;
        #pragma unroll
        for (int kg = 0; kg < 4; kg++)
            ldsm_x4(qa[kg][0], qa[kg][1], qa[kg][2], qa[kg][3], qaddr + kg * 32);
    }
    __syncthreads();

    const unsigned koff = ((ln & 7) + ((ln >> 4) << 3)) * KVROW + ((ln >> 3) & 1) * 16;
    const unsigned voff = ((ln & 7) + ((ln >> 3) & 1) * 8) * KVROW + (ln >> 4) * 16;

    #define ISSUE(ktg, buf) do {                                                   \
        unsigned kd = smb + (buf) * (2 * STG) + tid * KVROW;                       \
        const char* ks = qb + (size_t)((ktg) * 128 + tid) * 3072 + 1024 + h * 128; \
        _Pragma("unroll")                                                          \
        for (int c = 0; c < 8; c++) {                                              \
            cp16(kd + c * 16, ks + c * 16);                                        \
            cp16(kd + STG + c * 16, ks + 1024 + c * 16);                           \
        }                                                                          \
        asm volatile("cp.async.commit_group;");                                    \
    } while (0)

    float m0r = -1e30f, m1r = -1e30f, l0r = 0.f, l1r = 0.f;
    float o[8][4];
    #pragma unroll
    for (int nt = 0; nt < 8; nt++)
        #pragma unroll
        for (int i = 0; i < 4; i++) o[nt][i] = 0.f;

    ISSUE(0, 0);

    for (int kt = 0; kt < 16; kt++) {
        const int buf = kt & 1;
        if (kt < 15) {
            ISSUE(kt + 1, buf ^ 1);
            asm volatile("cp.async.wait_group 1;");
        } else {
            asm volatile("cp.async.wait_group 0;");
        }
        __syncthreads();
        const unsigned Kb = smb + buf * (2 * STG) + koff;
        const unsigned Vb = smb + buf * (2 * STG) + STG + voff;

        float s[16][4];
        #pragma unroll
        for (int nt = 0; nt < 16; nt++)
            #pragma unroll
            for (int i = 0; i < 4; i++) s[nt][i] = 0.f;
        #pragma unroll
        for (int j = 0; j < 8; j++) {
            #pragma unroll
            for (int kg = 0; kg < 4; kg++) {
                unsigned b0, b1, b2, b3;
                ldsm_x4(b0, b1, b2, b3, Kb + j * (16 * KVROW) + kg * 32);
                mma_bf16(s[2 * j],     qa[kg][0], qa[kg][1], qa[kg][2], qa[kg][3], b0, b1);
                mma_bf16(s[2 * j + 1], qa[kg][0], qa[kg][1], qa[kg][2], qa[kg][3], b2, b3);
            }
        }

        float mx0 = -1e30f, mx1 = -1e30f;
        #pragma unroll
        for (int nt = 0; nt < 16; nt++) {
            mx0 = fmaxf(mx0, fmaxf(s[nt][0], s[nt][1]));
            mx1 = fmaxf(mx1, fmaxf(s[nt][2], s[nt][3]));
        }
        mx0 = fmaxf(mx0, __shfl_xor_sync(0xffffffffu, mx0, 1));
        mx0 = fmaxf(mx0, __shfl_xor_sync(0xffffffffu, mx0, 2));
        mx1 = fmaxf(mx1, __shfl_xor_sync(0xffffffffu, mx1, 1));
        mx1 = fmaxf(mx1, __shfl_xor_sync(0xffffffffu, mx1, 2));
        const float mn0 = fmaxf(m0r, mx0), mn1 = fmaxf(m1r, mx1);
        const float al0 = __expf(m0r - mn0), al1 = __expf(m1r - mn1);
        m0r = mn0; m1r = mn1;
        float sum0 = 0.f, sum1 = 0.f;
        #pragma unroll
        for (int nt = 0; nt < 16; nt++) {
            s[nt][0] = __expf(s[nt][0] - mn0);
            s[nt][1] = __expf(s[nt][1] - mn0);
            s[nt][2] = __expf(s[nt][2] - mn1);
            s[nt][3] = __expf(s[nt][3] - mn1);
            sum0 += s[nt][0] + s[nt][1];
            sum1 += s[nt][2] + s[nt][3];
        }
        sum0 += __shfl_xor_sync(0xffffffffu, sum0, 1);
        sum0 += __shfl_xor_sync(0xffffffffu, sum0, 2);
        sum1 += __shfl_xor_sync(0xffffffffu, sum1, 1);
        sum1 += __shfl_xor_sync(0xffffffffu, sum1, 2);
        l0r = l0r * al0 + sum0;
        l1r = l1r * al1 + sum1;
        #pragma unroll
        for (int nt = 0; nt < 8; nt++) {
            o[nt][0] *= al0; o[nt][1] *= al0;
            o[nt][2] *= al1; o[nt][3] *= al1;
        }

        #pragma unroll
        for (int i = 0; i < 8; i++) {
            unsigned pa0 = pack_bf16(s[2 * i][0],     s[2 * i][1]);
            unsigned pa1 = pack_bf16(s[2 * i][2],     s[2 * i][3]);
            unsigned pa2 = pack_bf16(s[2 * i + 1][0], s[2 * i + 1][1]);
            unsigned pa3 = pack_bf16(s[2 * i + 1][2], s[2 * i + 1][3]);
            #pragma unroll
            for (int j = 0; j < 4; j++) {
                unsigned b0, b1, b2, b3;
                ldsm_x4t(b0, b1, b2, b3, Vb + i * (16 * KVROW) + j * 32);
                mma_bf16(o[2 * j],     pa0, pa1, pa2, pa3, b0, b1);
                mma_bf16(o[2 * j + 1], pa0, pa1, pa2, pa3, b2, b3);
            }
        }
        __syncthreads();
    }
    #undef ISSUE

    // ---- normalize + write bf16 ctx directly ----
    const float inv0 = 1.0f / l0r, inv1 = 1.0f / l1r;
    #pragma unroll
    for (int nt = 0; nt < 8; nt++) {
        const int n = h * 64 + 8 * nt + 2 * t;
        const size_t r0 = (size_t)(q0 + 16 * w + g) * D_;
        const size_t r1 = (size_t)(q0 + 16 * w + g + 8) * D_;
        *(unsigned*)&ctxb[r0 + n] = pack_bf16(o[nt][0] * inv0, o[nt][1] * inv0);
        *(unsigned*)&ctxb[r1 + n] = pack_bf16(o[nt][2] * inv1, o[nt][3] * inv1);
    }
}

// ---------------- per-row normalize ----------------
template<int N, bool AFFINE, bool ADD>
__global__ __launch_bounds__(128)
void rownorm(const float* __restrict__ src, const float* __restrict__ addv,
             const float* __restrict__ w, const float* __restrict__ bb,
             float* __restrict__ dst, __nv_bfloat16* __restrict__ dstb)
{
    constexpr int NPT = N / 128;
    const size_t base = (size_t)blockIdx.x * N;
    const int t = threadIdx.x;
    float v[NPT];
    float s = 0.f;
    #pragma unroll
    for (int i = 0; i < NPT; i++) { v[i] = src[base + t + i * 128]; s += v[i]; }
    __shared__ float sm[4];
    #pragma unroll
    for (int o = 16; o > 0; o >>= 1) s += __shfl_xor_sync(0xffffffffu, s, o);
    if ((t & 31) == 0) sm[t >> 5] = s;
    __syncthreads();
    s = sm[0] + sm[1] + sm[2] + sm[3];
    const float mean = s * (1.0f / N);
    float q = 0.f;
    #pragma unroll
    for (int i = 0; i < NPT; i++) { float d = v[i] - mean; q += d * d; }
    __syncthreads();
    #pragma unroll
    for (int o = 16; o > 0; o >>= 1) q += __shfl_xor_sync(0xffffffffu, q, o);
    if ((t & 31) == 0) sm[t >> 5] = q;
    __syncthreads();
    q = sm[0] + sm[1] + sm[2] + sm[3];
    const float r = rsqrtf(q * (1.0f / N) + EPSF);
    #pragma unroll
    for (int i = 0; i < NPT; i++) {
        int c = t + i * 128;
        float y = (v[i] - mean) * r;
        if (AFFINE) y = y * w[c] + bb[c];
        if (ADD)    y += addv[base + c];
        if (dst)  dst[base + c] = y;
        if (dstb) dstb[base + c] = __float2bfloat16(y);
    }
}

// ---------------- cdist to prototypes, min over P, logits ----------------
__global__ __launch_bounds__(128)
void cdist_logits(const float* __restrict__ z, const float* __restrict__ hi,
                  const float* __restrict__ neg, float* __restrict__ out)
{
    __shared__ float zr[Q_];
    __shared__ float dist[128];
    const int b = blockIdx.x, t = threadIdx.x;
    zr[t] = z[(size_t)b * Q_ + t];
    dist[t] = 3.4e38f;
    __syncthreads();
    if (t < P_) {
        const float* p = hi + (size_t)t * Q_;
        float s = 0.f;
        #pragma unroll 8
        for (int d = 0; d < Q_; d++) { float df = zr[d] - p[d]; s = fmaf(df, df, s); }
        dist[t] = sqrtf(s);
    } else if (t >= 64 && t < 64 + P_) {
        const float* p = neg + (size_t)(t - 64) * Q_;
        float s = 0.f;
        #pragma unroll 8
        for (int d = 0; d < Q_; d++) { float df = zr[d] - p[d]; s = fmaf(df, df, s); }
        dist[t] = sqrtf(s);
    }
    __syncthreads();
    if (t == 0) {
        float m = 3.4e38f;
        for (int i = 0; i < P_; i++) m = fminf(m, dist[i]);
        out[b * 2 + 1] = -m;
    }
    if (t == 32) {
        float m = 3.4e38f;
        for (int i = 0; i < P_; i++) m = fminf(m, dist[64 + i]);
        out[b * 2 + 0] = -m;
    }
}

// ---------------- host driver ----------------
extern "C" void kernel_launch(void* const* d_in, const int* in_sizes, int n_in,
                              void* d_out, int out_size)
{
    const float* x        = (const float*)d_in[0];
    const float* reduce_w = (const float*)d_in[1];
    const float* reduce_b = (const float*)d_in[2];
    const float* in_w     = (const float*)d_in[3];
    const float* in_b     = (const float*)d_in[4];
    const float* out_w    = (const float*)d_in[5];
    const float* out_b    = (const float*)d_in[6];
    const float* ff1_w    = (const float*)d_in[7];
    const float* ff1_b    = (const float*)d_in[8];
    const float* ff2_w    = (const float*)d_in[9];
    const float* ff2_b    = (const float*)d_in[10];
    const float* ln1_w    = (const float*)d_in[11];
    const float* ln1_b    = (const float*)d_in[12];
    const float* ln2_w    = (const float*)d_in[13];
    const float* ln2_b    = (const float*)d_in[14];
    const float* mlp_w1   = (const float*)d_in[15];
    const float* mlp_b1   = (const float*)d_in[16];
    const float* mlp_w2   = (const float*)d_in[17];
    const float* mlp_b2   = (const float*)d_in[18];
    const float* mlp_w3   = (const float*)d_in[19];
    const float* mlp_b3   = (const float*)d_in[20];
    const float* highlights = (const float*)d_in[21];
    const float* negatives  = (const float*)d_in[22];
    float* out = (float*)d_out;

    float *feat0, *feat, *buf1, *buf2, *z;
    __nv_bfloat16 *wbf, *qkvb, *xb, *ab1, *ab2, *ab3;
    cudaGetSymbolAddress((void**)&feat0, g_feat0);
    cudaGetSymbolAddress((void**)&feat,  g_feat);
    cudaGetSymbolAddress((void**)&buf1,  g_buf1);
    cudaGetSymbolAddress((void**)&buf2,  g_buf2);
    cudaGetSymbolAddress((void**)&qkvb,  g_qkvb);
    cudaGetSymbolAddress((void**)&xb,    g_xb);
    cudaGetSymbolAddress((void**)&ab1,   g_ab1);
    cudaGetSymbolAddress((void**)&ab2,   g_ab2);
    cudaGetSymbolAddress((void**)&ab3,   g_ab3);
    cudaGetSymbolAddress((void**)&z,     g_z);
    cudaGetSymbolAddress((void**)&wbf,   g_wbf);

    cudaFuncSetAttribute(attn_fused, cudaFuncAttributeMaxDynamicSharedMemorySize,
                         ATTN_SMEM);
    const int SM64  = 3 * (128 + 64) * 80;    // 46080
    const int SM128 = 3 * (128 + 128) * 80;   // 61440
    cudaFuncSetAttribute(gemm_bf16<64, 0, 0>,  cudaFuncAttributeMaxDynamicSharedMemorySize, SM64);
    cudaFuncSetAttribute(gemm_bf16<128, 0, 1>, cudaFuncAttributeMaxDynamicSharedMemorySize, SM128);
    cudaFuncSetAttribute(gemm_bf16<64, 2, 0>,  cudaFuncAttributeMaxDynamicSharedMemorySize, SM64);
    cudaFuncSetAttribute(gemm_bf16<64, 1, 2>,  cudaFuncAttributeMaxDynamicSharedMemorySize, SM64);

    // ---- convert all weights + x to bf16 in one launch ----
    Cvt9 cv;
    const float* srcs[9] = {reduce_w, in_w, out_w, ff1_w, ff2_w, mlp_w1, mlp_w2, mlp_w3, x};
    __nv_bfloat16* dsts[9] = {wbf + OFF_RED, wbf + OFF_IN, wbf + OFF_OUT, wbf + OFF_FF1,
                              wbf + OFF_FF2, wbf + OFF_M1, wbf + OFF_M2, wbf + OFF_M3, xb};
    const int n4s[9] = {D_ * DIN_ / 4, L_ * 3 * D_ * D_ / 4, L_ * D_ * D_ / 4,
                        L_ * D_ * D_ / 4, L_ * D_ * D_ / 4, D_ * D_ / 4, D_ * D_ / 4,
                        Q_ * D_ / 4, B_ * DIN_ / 4};
    cv.cum[0] = 0;
    for (int i = 0; i < 9; i++) {
        cv.s[i] = srcs[i];
        cv.d[i] = dsts[i];
        cv.cum[i + 1] = cv.cum[i] + n4s[i];
    }
    cvt_bf16_all<<<(cv.cum[9] + 255) / 256, 256>>>(cv);

    // feat0 = inorm(x @ reduce_w^T + b)
    gemm_bf16<64, 0, 0><<<dim3(D_ / 64, B_ / 128), 256, SM64>>>(
        xb, wbf + OFF_RED, reduce_b, nullptr, buf1, DIN_, D_);
    rownorm<D_, false, false><<<B_, 128>>>(buf1, nullptr, nullptr, nullptr, feat0, ab1);

    const float* featPrev = feat0;
    for (int l = 0; l < L_; l++) {
        gemm_bf16<128, 0, 1><<<dim3(3 * D_ / 128, B_ / 128), 256, SM128>>>(
            ab1, wbf + OFF_IN + (size_t)l * 3 * D_ * D_, in_b + l * 3 * D_, nullptr,
            qkvb, D_, 3 * D_);
        attn_fused<<<dim3(B_ / 64, H_), 128, ATTN_SMEM>>>(qkvb, ab3);
        gemm_bf16<64, 2, 0><<<dim3(D_ / 64, B_ / 128), 256, SM64>>>(
            ab3, wbf + OFF_OUT + (size_t)l * D_ * D_, out_b + l * D_, featPrev, buf1, D_, D_);
        rownorm<D_, true, false><<<B_, 128>>>(buf1, nullptr, ln1_w + l * D_, ln1_b + l * D_,
                                              feat, ab1);
        gemm_bf16<64, 1, 2><<<dim3(D_ / 64, B_ / 128), 256, SM64>>>(
            ab1, wbf + OFF_FF1 + (size_t)l * D_ * D_, ff1_b + l * D_, nullptr, ab2, D_, D_);
        gemm_bf16<64, 2, 0><<<dim3(D_ / 64, B_ / 128), 256, SM64>>>(
            ab2, wbf + OFF_FF2 + (size_t)l * D_ * D_, ff2_b + l * D_, feat, buf1, D_, D_);
        rownorm<D_, true, false><<<B_, 128>>>(buf1, nullptr, ln2_w + l * D_, ln2_b + l * D_,
                                              feat, ab1);
        featPrev = feat;
    }

    rownorm<D_, false, true><<<B_, 128>>>(feat, feat0, nullptr, nullptr, nullptr, ab1);

    gemm_bf16<64, 1, 2><<<dim3(D_ / 64, B_ / 128), 256, SM64>>>(
        ab1, wbf + OFF_M1, mlp_b1, nullptr, ab2, D_, D_);
    gemm_bf16<64, 1, 2><<<dim3(D_ / 64, B_ / 128), 256, SM64>>>(
        ab2, wbf + OFF_M2, mlp_b2, nullptr, ab3, D_, D_);
    gemm_bf16<64, 0, 0><<<dim3(Q_ / 64, B_ / 128), 256, SM64>>>(
        ab3, wbf + OFF_M3, mlp_b3, nullptr, buf2, D_, Q_);
    rownorm<Q_, false, false><<<B_, 128>>>(buf2, nullptr, nullptr, nullptr, z, nullptr);

    cdist_logits<<<B_, 128>>>(z, highlights, negatives, out);
}